// round 1
// baseline (speedup 1.0000x reference)
#include <cuda_runtime.h>
#include <math.h>

// Problem dims (fixed by setup_inputs)
#define BB    4096
#define INF_  2048
#define FEATF 2048
#define EE    512
#define NSN   1024
#define INV_T 10.0f

// ---------------- scratch (static device globals; no allocation) ------------
__device__ float g_feat[BB * FEATF];                 // 33.5 MB
__device__ float g_z[BB * EE];                       // 8.4 MB
__device__ float g_nz[BB * EE];                      // 8.4 MB
__device__ float g_ns[NSN * EE];                     // 2 MB
__device__ float g_scores[BB * NSN];                 // 16 MB
__device__ int   g_ind[BB];
__device__ float g_compat[(size_t)BB * BB];          // 64 MB
__device__ float g_abssim[NSN * NSN];                // 4 MB
__device__ float g_rl1[BB];
__device__ float g_rl2[NSN];

// ---------------- block reduction helpers -----------------------------------
__device__ __forceinline__ float blkRedSum(float v) {
    __shared__ float sh[33];
    int lane = threadIdx.x & 31, w = threadIdx.x >> 5;
    #pragma unroll
    for (int o = 16; o > 0; o >>= 1) v += __shfl_xor_sync(0xffffffffu, v, o);
    if (lane == 0) sh[w] = v;
    __syncthreads();
    int nw = blockDim.x >> 5;
    v = (threadIdx.x < (unsigned)nw) ? sh[threadIdx.x] : 0.f;
    if (w == 0) {
        #pragma unroll
        for (int o = 16; o > 0; o >>= 1) v += __shfl_xor_sync(0xffffffffu, v, o);
        if (lane == 0) sh[32] = v;
    }
    __syncthreads();
    float r = sh[32];
    __syncthreads();
    return r;
}

__device__ __forceinline__ float blkRedMax(float v) {
    __shared__ float sh[33];
    int lane = threadIdx.x & 31, w = threadIdx.x >> 5;
    #pragma unroll
    for (int o = 16; o > 0; o >>= 1) v = fmaxf(v, __shfl_xor_sync(0xffffffffu, v, o));
    if (lane == 0) sh[w] = v;
    __syncthreads();
    int nw = blockDim.x >> 5;
    v = (threadIdx.x < (unsigned)nw) ? sh[threadIdx.x] : -INFINITY;
    if (w == 0) {
        #pragma unroll
        for (int o = 16; o > 0; o >>= 1) v = fmaxf(v, __shfl_xor_sync(0xffffffffu, v, o));
        if (lane == 0) sh[32] = v;
    }
    __syncthreads();
    float r = sh[32];
    __syncthreads();
    return r;
}

// ---------------- GEMM: C[m,n] = scale*sum_k A[m,k]*B[g(n),k] (+bias) (relu) -
// A: [M,K] row-major, B: [N,K] row-major (NT gemm). M,N multiples of 128, K of 16.
template<bool RELU, bool GATHER, bool BIAS>
__global__ __launch_bounds__(256)
void gemm_nt(const float* __restrict__ A, const float* __restrict__ Bm,
             const float* __restrict__ bias, const int* __restrict__ gidx,
             float* __restrict__ C, int M, int N, int K, float scale)
{
    constexpr int BMt = 128, BNt = 128, BKt = 16;
    __shared__ float As[BKt][BMt + 4];
    __shared__ float Bs[BKt][BNt + 4];

    const int tid  = threadIdx.x;
    const int tcol = tid & 15;      // 0..15
    const int trow = tid >> 4;      // 0..15
    const long aBase = (long)blockIdx.y * BMt * K;

    float acc[8][8];
    #pragma unroll
    for (int i = 0; i < 8; i++)
        #pragma unroll
        for (int j = 0; j < 8; j++) acc[i][j] = 0.f;

    for (int k0 = 0; k0 < K; k0 += BKt) {
        // load A tile (128x16), transposed into smem
        #pragma unroll
        for (int l = 0; l < 2; l++) {
            int f   = tid + l * 256;
            int row = f >> 2;
            int kk  = (f & 3) << 2;
            float4 v = *(const float4*)(A + aBase + (long)row * K + k0 + kk);
            As[kk + 0][row] = v.x; As[kk + 1][row] = v.y;
            As[kk + 2][row] = v.z; As[kk + 3][row] = v.w;
        }
        // load B tile (128x16) with optional row gather
        #pragma unroll
        for (int l = 0; l < 2; l++) {
            int f   = tid + l * 256;
            int row = f >> 2;
            int kk  = (f & 3) << 2;
            int gn  = blockIdx.x * BNt + row;
            long srow = GATHER ? (long)gidx[gn] : (long)gn;
            float4 v = *(const float4*)(Bm + srow * K + k0 + kk);
            Bs[kk + 0][row] = v.x; Bs[kk + 1][row] = v.y;
            Bs[kk + 2][row] = v.z; Bs[kk + 3][row] = v.w;
        }
        __syncthreads();
        #pragma unroll
        for (int k = 0; k < BKt; k++) {
            float ra[8], rb[8];
            *(float4*)&ra[0] = *(const float4*)&As[k][trow * 4];
            *(float4*)&ra[4] = *(const float4*)&As[k][64 + trow * 4];
            *(float4*)&rb[0] = *(const float4*)&Bs[k][tcol * 4];
            *(float4*)&rb[4] = *(const float4*)&Bs[k][64 + tcol * 4];
            #pragma unroll
            for (int i = 0; i < 8; i++)
                #pragma unroll
                for (int j = 0; j < 8; j++)
                    acc[i][j] = fmaf(ra[i], rb[j], acc[i][j]);
        }
        __syncthreads();
    }

    #pragma unroll
    for (int i = 0; i < 8; i++) {
        int gm = blockIdx.y * BMt + ((i < 4) ? (trow * 4 + i) : (64 + trow * 4 + i - 4));
        #pragma unroll
        for (int jh = 0; jh < 2; jh++) {
            int cn = blockIdx.x * BNt + jh * 64 + tcol * 4;
            float4 v;
            v.x = acc[i][jh * 4 + 0] * scale;
            v.y = acc[i][jh * 4 + 1] * scale;
            v.z = acc[i][jh * 4 + 2] * scale;
            v.w = acc[i][jh * 4 + 3] * scale;
            if (BIAS) {
                v.x += bias[cn + 0]; v.y += bias[cn + 1];
                v.z += bias[cn + 2]; v.w += bias[cn + 3];
            }
            if (RELU) {
                v.x = fmaxf(v.x, 0.f); v.y = fmaxf(v.y, 0.f);
                v.z = fmaxf(v.z, 0.f); v.w = fmaxf(v.w, 0.f);
            }
            *(float4*)(C + (long)gm * N + cn) = v;
        }
    }
}

// ---------------- row-wise L2 normalize (F.normalize semantics) --------------
__global__ void l2norm_rows(const float* __restrict__ in, float* __restrict__ out, int cols)
{
    int row = blockIdx.x;
    const float4* p = (const float4*)(in + (long)row * cols);
    float4* q = (float4*)(out + (long)row * cols);
    int n4 = cols >> 2;
    float ss = 0.f;
    for (int c = threadIdx.x; c < n4; c += blockDim.x) {
        float4 v = p[c];
        ss += v.x * v.x + v.y * v.y + v.z * v.z + v.w * v.w;
    }
    float tot = blkRedSum(ss);
    float s = 1.f / fmaxf(sqrtf(tot), 1e-12f);
    for (int c = threadIdx.x; c < n4; c += blockDim.x) {
        float4 v = p[c];
        v.x *= s; v.y *= s; v.z *= s; v.w *= s;
        q[c] = v;
    }
}

// ---------------- per-row argmax (first-index tie-break, jnp semantics) ------
__global__ void argmax_rows(const float* __restrict__ S, int cols, int* __restrict__ ind)
{
    int row = blockIdx.x;
    const float* p = S + (long)row * cols;
    float best = -INFINITY; int bi = 0x7fffffff;
    for (int c = threadIdx.x; c < cols; c += blockDim.x) {
        float v = p[c];
        if (v > best) { best = v; bi = c; }   // per-thread cols increase -> keeps first
    }
    __shared__ float sv[256];
    __shared__ int   si[256];
    sv[threadIdx.x] = best; si[threadIdx.x] = bi;
    __syncthreads();
    for (int s = 128; s > 0; s >>= 1) {
        if (threadIdx.x < (unsigned)s) {
            float ov = sv[threadIdx.x + s]; int oi = si[threadIdx.x + s];
            if (ov > sv[threadIdx.x] || (ov == sv[threadIdx.x] && oi < si[threadIdx.x])) {
                sv[threadIdx.x] = ov; si[threadIdx.x] = oi;
            }
        }
        __syncthreads();
    }
    if (threadIdx.x == 0) ind[row] = si[0];
}

// ---------------- gather abs_state rows into output --------------------------
__global__ void gather_out(float* __restrict__ out, const float* __restrict__ ns,
                           const int* __restrict__ ind)
{
    int row = blockIdx.x;
    const float4* p = (const float4*)(ns + (long)ind[row] * EE);
    float4* q = (float4*)(out + (long)row * EE);
    q[threadIdx.x] = p[threadIdx.x];          // 128 threads * float4 = 512 floats
}

// ---------------- per-row: -log_softmax(softmax(S))[row,row] -----------------
__global__ void row_ce(const float* __restrict__ S, int cols, float* __restrict__ rl)
{
    int row = blockIdx.x;
    const float* p = S + (long)row * cols;
    float m = -INFINITY;
    for (int c = threadIdx.x; c < cols; c += blockDim.x) m = fmaxf(m, p[c]);
    m = blkRedMax(m);
    float se = 0.f;
    for (int c = threadIdx.x; c < cols; c += blockDim.x) se += expf(p[c] - m);
    se = blkRedSum(se);
    float inv = 1.f / se;
    float t = 0.f;
    for (int c = threadIdx.x; c < cols; c += blockDim.x) t += expf(expf(p[c] - m) * inv);
    t = blkRedSum(t);
    if (threadIdx.x == 0) {
        float pd = expf(p[row] - m) * inv;     // probs diagonal
        rl[row] = -(pd - logf(t));             // -(log_softmax of probs at diag)
    }
}

// ---------------- final loss: mean over both CE terms, single block ----------
__global__ void final_loss(float* __restrict__ out, long idx)
{
    float s1 = 0.f;
    for (int i = threadIdx.x; i < BB; i += 1024) s1 += g_rl1[i];
    float s2 = (threadIdx.x < NSN) ? g_rl2[threadIdx.x] : 0.f;
    float v = s1 * (1.0f / (float)BB) + s2 * (1.0f / (float)NSN);
    v = blkRedSum(v);
    if (threadIdx.x == 0) out[idx] = v;
}

// ---------------- launch ------------------------------------------------------
extern "C" void kernel_launch(void* const* d_in, const int* in_sizes, int n_in,
                              void* d_out, int out_size)
{
    const float* x          = (const float*)d_in[0];
    const float* body_W     = (const float*)d_in[1];
    const float* body_b     = (const float*)d_in[2];
    const float* fc_W       = (const float*)d_in[3];
    const float* fc_b       = (const float*)d_in[4];
    const float* abs_states = (const float*)d_in[5];
    float* out = (float*)d_out;

    float *feat, *z, *nz, *ns, *scores, *compat, *abssim, *rl1, *rl2;
    int* ind;
    cudaGetSymbolAddress((void**)&feat,   g_feat);
    cudaGetSymbolAddress((void**)&z,      g_z);
    cudaGetSymbolAddress((void**)&nz,     g_nz);
    cudaGetSymbolAddress((void**)&ns,     g_ns);
    cudaGetSymbolAddress((void**)&scores, g_scores);
    cudaGetSymbolAddress((void**)&ind,    g_ind);
    cudaGetSymbolAddress((void**)&compat, g_compat);
    cudaGetSymbolAddress((void**)&abssim, g_abssim);
    cudaGetSymbolAddress((void**)&rl1,    g_rl1);
    cudaGetSymbolAddress((void**)&rl2,    g_rl2);

    // 1) feat = relu(x @ body_W^T + body_b)           [4096, 2048]
    gemm_nt<true, false, true><<<dim3(FEATF / 128, BB / 128), 256>>>(
        x, body_W, body_b, nullptr, feat, BB, FEATF, INF_, 1.0f);

    // 2) z = feat @ fc_W^T + fc_b                     [4096, 512]
    gemm_nt<false, false, true><<<dim3(EE / 128, BB / 128), 256>>>(
        feat, fc_W, fc_b, nullptr, z, BB, EE, FEATF, 1.0f);

    // 3) normalize
    l2norm_rows<<<BB, 128>>>(z, nz, EE);
    l2norm_rows<<<NSN, 128>>>(abs_states, ns, EE);

    // 4) scores = (nz @ ns^T) / T                     [4096, 1024]
    gemm_nt<false, false, false><<<dim3(NSN / 128, BB / 128), 256>>>(
        nz, ns, nullptr, nullptr, scores, BB, NSN, EE, INV_T);

    // 5) argmax rows -> ind ; 6) abs_state output = ns[ind]
    argmax_rows<<<BB, 256>>>(scores, NSN, ind);
    gather_out<<<BB, 128>>>(out, ns, ind);

    // 7) compatible logits = (nz @ ns[ind]^T) / T     [4096, 4096]
    gemm_nt<false, true, false><<<dim3(BB / 128, BB / 128), 256>>>(
        nz, ns, nullptr, ind, compat, BB, BB, EE, INV_T);
    row_ce<<<BB, 256>>>(compat, BB, rl1);

    // 8) abs_sim logits = (ns @ ns^T) / T             [1024, 1024]
    gemm_nt<false, false, false><<<dim3(NSN / 128, NSN / 128), 256>>>(
        ns, ns, nullptr, nullptr, abssim, NSN, NSN, EE, INV_T);
    row_ce<<<NSN, 256>>>(abssim, NSN, rl2);

    // 9) loss scalar appended after abs_state
    if (out_size > BB * EE) {
        final_loss<<<1, 1024>>>(out, (long)BB * EE);
    }
}

// round 3
// speedup vs baseline: 1.0840x; 1.0840x over previous
#include <cuda_runtime.h>
#include <cuda_bf16.h>
#include <cstdint>
#include <math.h>

// Problem dims (fixed by setup_inputs)
#define BB    4096
#define INF_  2048
#define FEATF 2048
#define EE    512
#define NSN   1024
#define INV_T 10.0f

// ---------------- scratch (static device globals; no allocation) ------------
__device__ __nv_bfloat16 g_x2 [(size_t)BB   * 2 * INF_ ];   // [4096, 4096] hi|lo
__device__ __nv_bfloat16 g_w1 [(size_t)FEATF* 2 * INF_ ];   // [2048, 4096]
__device__ __nv_bfloat16 g_w2 [(size_t)EE   * 2 * FEATF];   // [512, 4096]
__device__ __nv_bfloat16 g_f2 [(size_t)BB   * 2 * FEATF];   // [4096, 4096]
__device__ float         g_z  [(size_t)BB * EE];
__device__ __nv_bfloat16 g_nz2[(size_t)BB * 2 * EE];        // [4096, 1024]
__device__ float         g_ns [(size_t)NSN * EE];
__device__ __nv_bfloat16 g_ns2[(size_t)NSN * 2 * EE];       // [1024, 1024]
__device__ float         g_scores[(size_t)BB * NSN];
__device__ int           g_ind[BB];
__device__ __nv_bfloat16 g_cb2[(size_t)BB * 2 * EE];        // gathered B for compat
__device__ float         g_compat[(size_t)BB * BB];         // 64 MB
__device__ float         g_abssim[(size_t)NSN * NSN];
__device__ float         g_rl1[BB];
__device__ float         g_rl2[NSN];

// ---------------- low-level helpers ------------------------------------------
__device__ __forceinline__ uint32_t smem_u32(const void* p) {
    uint32_t a;
    asm("{ .reg .u64 t; cvta.to.shared.u64 t, %1; cvt.u32.u64 %0, t; }" : "=r"(a) : "l"(p));
    return a;
}
__device__ __forceinline__ void cpasync16(uint32_t dst, const void* src) {
    asm volatile("cp.async.cg.shared.global [%0], [%1], 16;" :: "r"(dst), "l"(src) : "memory");
}
#define CP_COMMIT() asm volatile("cp.async.commit_group;" ::: "memory")
#define CP_WAIT(n)  asm volatile("cp.async.wait_group %0;" :: "n"(n) : "memory")

__device__ __forceinline__ void ldm_x4(uint32_t& r0, uint32_t& r1, uint32_t& r2, uint32_t& r3,
                                       uint32_t addr) {
    asm volatile("ldmatrix.sync.aligned.m8n8.x4.shared.b16 {%0,%1,%2,%3}, [%4];"
                 : "=r"(r0), "=r"(r1), "=r"(r2), "=r"(r3) : "r"(addr));
}
__device__ __forceinline__ void mma16816(float* c, const uint32_t* a, const uint32_t* b) {
    asm volatile(
        "mma.sync.aligned.m16n8k16.row.col.f32.bf16.bf16.f32 "
        "{%0,%1,%2,%3},{%4,%5,%6,%7},{%8,%9},{%0,%1,%2,%3};"
        : "+f"(c[0]), "+f"(c[1]), "+f"(c[2]), "+f"(c[3])
        : "r"(a[0]), "r"(a[1]), "r"(a[2]), "r"(a[3]), "r"(b[0]), "r"(b[1]));
}
// smem byte offset for (row, 16B-chunk c of 4) in a tile with 64B logical rows,
// packed 2 rows / 128B line, XOR-swizzled: conflict-free for ldmatrix 8-row reads.
__device__ __forceinline__ uint32_t swz(int row, int c) {
    return (uint32_t)(((row >> 1) << 7) + ((((((row & 1) << 2) | c)) ^ ((row >> 1) & 7)) << 4));
}

// ---------------- block reduction --------------------------------------------
__device__ __forceinline__ float blkRedSum(float v) {
    __shared__ float sh[33];
    int lane = threadIdx.x & 31, w = threadIdx.x >> 5;
    #pragma unroll
    for (int o = 16; o > 0; o >>= 1) v += __shfl_xor_sync(0xffffffffu, v, o);
    if (lane == 0) sh[w] = v;
    __syncthreads();
    int nw = blockDim.x >> 5;
    v = (threadIdx.x < (unsigned)nw) ? sh[threadIdx.x] : 0.f;
    if (w == 0) {
        #pragma unroll
        for (int o = 16; o > 0; o >>= 1) v += __shfl_xor_sync(0xffffffffu, v, o);
        if (lane == 0) sh[32] = v;
    }
    __syncthreads();
    float r = sh[32];
    __syncthreads();
    return r;
}

// =============================================================================
// mma.sync bf16 split GEMM. 3 passes: Ahi*Bhi + Ahi*Blo + Alo*Bhi (fp32 accum)
// A: [M, 2K] bf16 (hi|lo) row-major (ldA), B: [N, 2K] same (ldB). NT product.
// Tile BMxBN(=128), BK=32, 4-stage cp.async, 256 threads.
// MODE 0: Cf = scale * D          MODE 1: Cf = D + bias
// MODE 2: relu(D + bias) -> bf16 hi/lo into C2 at [r][c] and [r][loOff + c]
// =============================================================================
template<int MODE, int BM>
__global__ __launch_bounds__(256)
void gemm_tc(const __nv_bfloat16* __restrict__ A, int ldA,
             const __nv_bfloat16* __restrict__ B, int ldB,
             int K, int Ncols,
             const float* __restrict__ bias, float scale,
             float* __restrict__ Cf, __nv_bfloat16* __restrict__ C2,
             int ldC2, int loOff)
{
    constexpr int BN = 128, STAGES = 4;
    constexpr int WM = 64;
    constexpr int WN = (BM == 256) ? 64 : 32;
    constexpr int MI = WM / 16;              // 4
    constexpr int NI = WN / 8;               // 8 or 4
    constexpr int NWN = BN / WN;             // warps along n
    constexpr uint32_t ABYTES = BM * 64;
    constexpr uint32_t BBYTES = BN * 64;
    constexpr uint32_t STAGE = ABYTES + BBYTES;

    extern __shared__ __align__(128) char smraw[];
    const uint32_t sm0 = smem_u32(smraw);

    const int tid  = threadIdx.x;
    const int wid  = tid >> 5;
    const int lane = tid & 31;
    const int wm   = wid / NWN;
    const int wn   = wid % NWN;

    const int bm = blockIdx.y * BM;
    const int bn = blockIdx.x * BN;
    const int nc = K >> 5;                   // 32-wide k chunks per pass
    const int total = 3 * nc;

    float acc[MI][NI][4];
    #pragma unroll
    for (int i = 0; i < MI; i++)
        #pragma unroll
        for (int j = 0; j < NI; j++)
            #pragma unroll
            for (int q = 0; q < 4; q++) acc[i][j][q] = 0.f;

    auto load_stage = [&](int t, int buf) {
        int p = t / nc, cc = t - p * nc;
        long acol = (p == 2 ? (long)K : 0) + (long)cc * 32;
        long bcol = (p == 1 ? (long)K : 0) + (long)cc * 32;
        uint32_t aB = sm0 + buf * STAGE;
        uint32_t bBs = aB + ABYTES;
        #pragma unroll
        for (int i = 0; i < BM * 4 / 256; i++) {
            int u = tid + i * 256; int r = u >> 2, c = u & 3;
            cpasync16(aB + swz(r, c), A + (long)(bm + r) * ldA + acol + c * 8);
        }
        #pragma unroll
        for (int i = 0; i < 2; i++) {
            int u = tid + i * 256; int r = u >> 2, c = u & 3;
            cpasync16(bBs + swz(r, c), B + (long)(bn + r) * ldB + bcol + c * 8);
        }
    };

    auto compute_stage = [&](int buf) {
        uint32_t aB = sm0 + buf * STAGE;
        uint32_t bB = aB + ABYTES;
        #pragma unroll
        for (int ks = 0; ks < 2; ks++) {
            uint32_t af[MI][4], bf[NI][2];
            int cch = ks * 2 + (lane >> 4);
            #pragma unroll
            for (int mi = 0; mi < MI; mi++) {
                int r = wm * WM + mi * 16 + (lane & 15);
                ldm_x4(af[mi][0], af[mi][1], af[mi][2], af[mi][3], aB + swz(r, cch));
            }
            #pragma unroll
            for (int nj = 0; nj < NI / 2; nj++) {
                int r = wn * WN + nj * 16 + (lane & 15);
                uint32_t q0, q1, q2, q3;
                ldm_x4(q0, q1, q2, q3, bB + swz(r, cch));
                bf[2 * nj][0] = q0; bf[2 * nj + 1][0] = q1;
                bf[2 * nj][1] = q2; bf[2 * nj + 1][1] = q3;
            }
            #pragma unroll
            for (int mi = 0; mi < MI; mi++)
                #pragma unroll
                for (int ni = 0; ni < NI; ni++)
                    mma16816(acc[mi][ni], af[mi], bf[ni]);
        }
    };

    // prologue: stages 0..STAGES-2
    #pragma unroll
    for (int s = 0; s < STAGES - 1; s++) {
        load_stage(s, s);
        CP_COMMIT();
    }

    for (int t = 0; t < total; t++) {
        CP_WAIT(STAGES - 2);
        __syncthreads();
        if (t + STAGES - 1 < total) {
            load_stage(t + STAGES - 1, (t + STAGES - 1) % STAGES);
            CP_COMMIT();
        }
        compute_stage(t % STAGES);
    }

    // ---- epilogue: d0,d1 at (r0, c0..c0+1); d2,d3 at (r0+8, ...)
    #pragma unroll
    for (int mi = 0; mi < MI; mi++) {
        int r0 = bm + wm * WM + mi * 16 + (lane >> 2);
        #pragma unroll
        for (int ni = 0; ni < NI; ni++) {
            int c0 = bn + wn * WN + ni * 8 + 2 * (lane & 3);
            float d0 = acc[mi][ni][0], d1 = acc[mi][ni][1];
            float d2 = acc[mi][ni][2], d3 = acc[mi][ni][3];
            if (MODE == 0) {
                float2 u0 = { d0 * scale, d1 * scale };
                float2 u1 = { d2 * scale, d3 * scale };
                *(float2*)(Cf + (long)r0 * Ncols + c0) = u0;
                *(float2*)(Cf + (long)(r0 + 8) * Ncols + c0) = u1;
            } else if (MODE == 1) {
                float b0 = __ldg(bias + c0), b1 = __ldg(bias + c0 + 1);
                float2 u0 = { d0 + b0, d1 + b1 };
                float2 u1 = { d2 + b0, d3 + b1 };
                *(float2*)(Cf + (long)r0 * Ncols + c0) = u0;
                *(float2*)(Cf + (long)(r0 + 8) * Ncols + c0) = u1;
            } else {
                float b0 = __ldg(bias + c0), b1 = __ldg(bias + c0 + 1);
                float v0 = fmaxf(d0 + b0, 0.f), v1 = fmaxf(d1 + b1, 0.f);
                float v2 = fmaxf(d2 + b0, 0.f), v3 = fmaxf(d3 + b1, 0.f);
                __nv_bfloat16 h0 = __float2bfloat16(v0), h1 = __float2bfloat16(v1);
                __nv_bfloat16 h2 = __float2bfloat16(v2), h3 = __float2bfloat16(v3);
                __nv_bfloat16 l0 = __float2bfloat16(v0 - __bfloat162float(h0));
                __nv_bfloat16 l1 = __float2bfloat16(v1 - __bfloat162float(h1));
                __nv_bfloat16 l2 = __float2bfloat16(v2 - __bfloat162float(h2));
                __nv_bfloat16 l3 = __float2bfloat16(v3 - __bfloat162float(h3));
                __nv_bfloat162 hp0; hp0.x = h0; hp0.y = h1;
                __nv_bfloat162 hp1; hp1.x = h2; hp1.y = h3;
                __nv_bfloat162 lp0; lp0.x = l0; lp0.y = l1;
                __nv_bfloat162 lp1; lp1.x = l2; lp1.y = l3;
                *(__nv_bfloat162*)(C2 + (long)r0 * ldC2 + c0) = hp0;
                *(__nv_bfloat162*)(C2 + (long)(r0 + 8) * ldC2 + c0) = hp1;
                *(__nv_bfloat162*)(C2 + (long)r0 * ldC2 + loOff + c0) = lp0;
                *(__nv_bfloat162*)(C2 + (long)(r0 + 8) * ldC2 + loOff + c0) = lp1;
            }
        }
    }
}

// ---------------- fp32 -> bf16 hi/lo split (layout [R, 2K], hi|lo) -----------
__global__ void cvt_split(const float4* __restrict__ in, __nv_bfloat16* __restrict__ out,
                          int kshift, int n4)
{
    int i = blockIdx.x * blockDim.x + threadIdx.x;
    if (i >= n4) return;
    float4 v = in[i];
    long e = (long)i * 4;
    int K = 1 << kshift;
    long r = e >> kshift;
    int k = (int)(e & (K - 1));
    long base = r * (2L * K) + k;
    float f[4] = {v.x, v.y, v.z, v.w};
    __nv_bfloat16 h[4], l[4];
    #pragma unroll
    for (int j = 0; j < 4; j++) {
        h[j] = __float2bfloat16(f[j]);
        l[j] = __float2bfloat16(f[j] - __bfloat162float(h[j]));
    }
    __nv_bfloat162 p0; p0.x = h[0]; p0.y = h[1];
    __nv_bfloat162 p1; p1.x = h[2]; p1.y = h[3];
    __nv_bfloat162 q0; q0.x = l[0]; q0.y = l[1];
    __nv_bfloat162 q1; q1.x = l[2]; q1.y = l[3];
    *(__nv_bfloat162*)(out + base + 0) = p0;
    *(__nv_bfloat162*)(out + base + 2) = p1;
    *(__nv_bfloat162*)(out + base + K + 0) = q0;
    *(__nv_bfloat162*)(out + base + K + 2) = q1;
}

// ---------------- row-wise L2 normalize + split (K = 512, 128 threads) -------
__global__ void l2norm_split(const float* __restrict__ in,
                             __nv_bfloat16* __restrict__ out2,
                             float* __restrict__ outf)
{
    int row = blockIdx.x;
    const float4* p = (const float4*)(in + (long)row * EE);
    float4 v = p[threadIdx.x];
    float ss = v.x*v.x + v.y*v.y + v.z*v.z + v.w*v.w;
    float tot = blkRedSum(ss);
    float s = 1.f / fmaxf(sqrtf(tot), 1e-12f);
    v.x *= s; v.y *= s; v.z *= s; v.w *= s;
    if (outf) ((float4*)(outf + (long)row * EE))[threadIdx.x] = v;
    long base = (long)row * (2 * EE) + threadIdx.x * 4;
    float f[4] = {v.x, v.y, v.z, v.w};
    __nv_bfloat16 h[4], l[4];
    #pragma unroll
    for (int j = 0; j < 4; j++) {
        h[j] = __float2bfloat16(f[j]);
        l[j] = __float2bfloat16(f[j] - __bfloat162float(h[j]));
    }
    __nv_bfloat162 p0; p0.x = h[0]; p0.y = h[1];
    __nv_bfloat162 p1; p1.x = h[2]; p1.y = h[3];
    __nv_bfloat162 q0; q0.x = l[0]; q0.y = l[1];
    __nv_bfloat162 q1; q1.x = l[2]; q1.y = l[3];
    *(__nv_bfloat162*)(out2 + base + 0) = p0;
    *(__nv_bfloat162*)(out2 + base + 2) = p1;
    *(__nv_bfloat162*)(out2 + base + EE + 0) = q0;
    *(__nv_bfloat162*)(out2 + base + EE + 2) = q1;
}

// ---------------- per-row argmax (first-index tie-break) ---------------------
__global__ void argmax_rows(const float* __restrict__ S, int cols, int* __restrict__ ind)
{
    int row = blockIdx.x;
    const float* p = S + (long)row * cols;
    float best = -INFINITY; int bi = 0x7fffffff;
    for (int c = threadIdx.x; c < cols; c += blockDim.x) {
        float v = p[c];
        if (v > best) { best = v; bi = c; }
    }
    __shared__ float sv[256];
    __shared__ int   si[256];
    sv[threadIdx.x] = best; si[threadIdx.x] = bi;
    __syncthreads();
    for (int s = 128; s > 0; s >>= 1) {
        if (threadIdx.x < (unsigned)s) {
            float ov = sv[threadIdx.x + s]; int oi = si[threadIdx.x + s];
            if (ov > sv[threadIdx.x] || (ov == sv[threadIdx.x] && oi < si[threadIdx.x])) {
                sv[threadIdx.x] = ov; si[threadIdx.x] = oi;
            }
        }
        __syncthreads();
    }
    if (threadIdx.x == 0) ind[row] = si[0];
}

// ---------------- gathers ----------------------------------------------------
__global__ void gather_out(float* __restrict__ out, const float* __restrict__ ns,
                           const int* __restrict__ ind)
{
    int row = blockIdx.x;
    const float4* p = (const float4*)(ns + (long)ind[row] * EE);
    float4* q = (float4*)(out + (long)row * EE);
    q[threadIdx.x] = p[threadIdx.x];
}
__global__ void gather_rows_bf16(__nv_bfloat16* __restrict__ dst,
                                 const __nv_bfloat16* __restrict__ src,
                                 const int* __restrict__ ind)
{
    int row = blockIdx.x;
    const uint4* s = (const uint4*)(src + (long)ind[row] * (2 * EE));
    uint4* d = (uint4*)(dst + (long)row * (2 * EE));
    d[threadIdx.x] = s[threadIdx.x];
}

// ---------------- fast exp on FMA/ALU pipes (x in [-30, 0.5]) ----------------
__device__ __forceinline__ float fexp(float x) {
    float y = x * 1.4426950408889634f;
    float m = y + 12582912.0f;               // round-to-nearest integer
    float i = m - 12582912.0f;
    float r = y - i;                         // [-0.5, 0.5]
    float p = 9.61812910762848e-3f;          // Taylor of 2^r
    p = fmaf(p, r, 5.55041086648216e-2f);
    p = fmaf(p, r, 2.40226506959101e-1f);
    p = fmaf(p, r, 6.93147180559945e-1f);
    p = fmaf(p, r, 1.0f);
    int sc = (__float_as_int(m) - 0x4B400000 + 127) << 23;
    return p * __int_as_float(sc);
}

// ---------------- per-row: -log_softmax(softmax(S))[row,row] -----------------
// scores bounded by 1/T=10 -> fixed shift M=10 (exact softmax invariance).
// One exp pass; t = Sum exp(q) via series: N + S1/Z + S2/(2Z^2) + S3/(6Z^3), Z=S1.
__global__ void row_ce(const float* __restrict__ S, int cols, float* __restrict__ rl)
{
    int row = blockIdx.x;
    const float* p = S + (long)row * cols;
    __shared__ float spd;
    float S1 = 0.f, S2 = 0.f, S3 = 0.f;
    int iter = 0;
    for (int c = threadIdx.x; c < cols; c += blockDim.x, iter++) {
        float s = p[c] - 10.0f;
        float e = (iter & 1) ? fexp(s) : __expf(s);   // use both pipes
        if (c == row) spd = e;
        float e2 = e * e;
        S1 += e;
        S2 += e2;
        S3 = fmaf(e2, e, S3);
    }
    S1 = blkRedSum(S1);
    S2 = blkRedSum(S2);
    S3 = blkRedSum(S3);
    if (threadIdx.x == 0) {
        float Z = S1;
        float t = (float)cols + 1.0f + S2 / (2.0f * Z * Z) + S3 / (6.0f * Z * Z * Z);
        float pd = spd / Z;
        rl[row] = -(pd - logf(t));
    }
}

// ---------------- final loss -------------------------------------------------
__global__ void final_loss(float* __restrict__ out, long idx)
{
    float s1 = 0.f;
    for (int i = threadIdx.x; i < BB; i += 1024) s1 += g_rl1[i];
    float s2 = (threadIdx.x < NSN) ? g_rl2[threadIdx.x] : 0.f;
    float v = s1 * (1.0f / (float)BB) + s2 * (1.0f / (float)NSN);
    v = blkRedSum(v);
    if (threadIdx.x == 0) out[idx] = v;
}

// ---------------- launch ------------------------------------------------------
extern "C" void kernel_launch(void* const* d_in, const int* in_sizes, int n_in,
                              void* d_out, int out_size)
{
    const float* x          = (const float*)d_in[0];
    const float* body_W     = (const float*)d_in[1];
    const float* body_b     = (const float*)d_in[2];
    const float* fc_W       = (const float*)d_in[3];
    const float* fc_b       = (const float*)d_in[4];
    const float* abs_states = (const float*)d_in[5];
    float* out = (float*)d_out;

    __nv_bfloat16 *x2, *w1, *w2, *f2, *nz2, *ns2, *cb2;
    float *z, *ns, *scores, *compat, *abssim, *rl1, *rl2;
    int* ind;
    cudaGetSymbolAddress((void**)&x2,  g_x2);
    cudaGetSymbolAddress((void**)&w1,  g_w1);
    cudaGetSymbolAddress((void**)&w2,  g_w2);
    cudaGetSymbolAddress((void**)&f2,  g_f2);
    cudaGetSymbolAddress((void**)&z,   g_z);
    cudaGetSymbolAddress((void**)&nz2, g_nz2);
    cudaGetSymbolAddress((void**)&ns,  g_ns);
    cudaGetSymbolAddress((void**)&ns2, g_ns2);
    cudaGetSymbolAddress((void**)&scores, g_scores);
    cudaGetSymbolAddress((void**)&ind, g_ind);
    cudaGetSymbolAddress((void**)&cb2, g_cb2);
    cudaGetSymbolAddress((void**)&compat, g_compat);
    cudaGetSymbolAddress((void**)&abssim, g_abssim);
    cudaGetSymbolAddress((void**)&rl1, g_rl1);
    cudaGetSymbolAddress((void**)&rl2, g_rl2);

    const int SM256 = 4 * (256 * 64 + 128 * 64);   // 98304
    const int SM128 = 4 * (128 * 64 + 128 * 64);   // 65536
    cudaFuncSetAttribute(gemm_tc<2,256>, cudaFuncAttributeMaxDynamicSharedMemorySize, SM256);
    cudaFuncSetAttribute(gemm_tc<0,256>, cudaFuncAttributeMaxDynamicSharedMemorySize, SM256);
    cudaFuncSetAttribute(gemm_tc<1,128>, cudaFuncAttributeMaxDynamicSharedMemorySize, SM128);
    cudaFuncSetAttribute(gemm_tc<0,128>, cudaFuncAttributeMaxDynamicSharedMemorySize, SM128);

    // 0) split-convert inputs to bf16 hi/lo
    cvt_split<<<(BB * INF_ / 4 + 255) / 256, 256>>>((const float4*)x, x2, 11, BB * INF_ / 4);
    cvt_split<<<(FEATF * INF_ / 4 + 255) / 256, 256>>>((const float4*)body_W, w1, 11, FEATF * INF_ / 4);
    cvt_split<<<(EE * FEATF / 4 + 255) / 256, 256>>>((const float4*)fc_W, w2, 11, EE * FEATF / 4);

    // 1) feat = relu(x @ body_W^T + b) -> split bf16 directly   [4096, 2048]
    gemm_tc<2,256><<<dim3(FEATF / 128, BB / 256), 256, SM256>>>(
        x2, 2 * INF_, w1, 2 * INF_, INF_, FEATF, body_b, 1.f,
        nullptr, f2, 2 * FEATF, FEATF);

    // 2) z = feat @ fc_W^T + b                                  [4096, 512]
    gemm_tc<1,128><<<dim3(EE / 128, BB / 128), 256, SM128>>>(
        f2, 2 * FEATF, w2, 2 * FEATF, FEATF, EE, fc_b, 1.f,
        z, nullptr, 0, 0);

    // 3) normalize (+split)
    l2norm_split<<<BB, 128>>>(z, nz2, nullptr);
    l2norm_split<<<NSN, 128>>>(abs_states, ns2, ns);

    // 4) scores = (nz @ ns^T) / T                               [4096, 1024]
    gemm_tc<0,128><<<dim3(NSN / 128, BB / 128), 256, SM128>>>(
        nz2, 2 * EE, ns2, 2 * EE, EE, NSN, nullptr, INV_T,
        scores, nullptr, 0, 0);

    // 5) argmax -> ind ; output abs_state = ns[ind]
    argmax_rows<<<BB, 256>>>(scores, NSN, ind);
    gather_out<<<BB, 128>>>(out, ns, ind);
    gather_rows_bf16<<<BB, 128>>>(cb2, ns2, ind);

    // 6) compatible = (nz @ ns[ind]^T) / T                      [4096, 4096]
    gemm_tc<0,256><<<dim3(BB / 128, BB / 256), 256, SM256>>>(
        nz2, 2 * EE, cb2, 2 * EE, EE, BB, nullptr, INV_T,
        compat, nullptr, 0, 0);
    row_ce<<<BB, 256>>>(compat, BB, rl1);

    // 7) abs_sim = (ns @ ns^T) / T                              [1024, 1024]
    gemm_tc<0,128><<<dim3(NSN / 128, NSN / 128), 256, SM128>>>(
        ns2, 2 * EE, ns2, 2 * EE, EE, NSN, nullptr, INV_T,
        abssim, nullptr, 0, 0);
    row_ce<<<NSN, 256>>>(abssim, NSN, rl2);

    // 8) loss scalar appended after abs_state
    if (out_size > BB * EE) {
        final_loss<<<1, 1024>>>(out, (long)BB * EE);
    }
}

// round 4
// speedup vs baseline: 2.0640x; 1.9040x over previous
#include <cuda_runtime.h>
#include <cuda_bf16.h>
#include <cstdint>
#include <math.h>

// Problem dims (fixed by setup_inputs)
#define BB    4096
#define INF_  2048
#define FEATF 2048
#define EE    512
#define NSN   1024
#define INV_T 10.0f

// ---------------- scratch (static device globals; no allocation) ------------
__device__ __nv_bfloat16 g_x2 [(size_t)BB   * 2 * INF_ ];
__device__ __nv_bfloat16 g_w1 [(size_t)FEATF* 2 * INF_ ];
__device__ __nv_bfloat16 g_w2 [(size_t)EE   * 2 * FEATF];
__device__ __nv_bfloat16 g_f2 [(size_t)BB   * 2 * FEATF];
__device__ float         g_z  [(size_t)BB * EE];
__device__ __nv_bfloat16 g_nz2[(size_t)BB * 2 * EE];
__device__ float         g_ns [(size_t)NSN * EE];
__device__ __nv_bfloat16 g_ns2[(size_t)NSN * 2 * EE];
__device__ float         g_scores[(size_t)BB * NSN];
__device__ int           g_ind[BB];
__device__ __nv_bfloat16 g_cb2[(size_t)BB * 2 * EE];
__device__ float         g_compat[(size_t)BB * BB];
__device__ float         g_abssim[(size_t)NSN * NSN];
__device__ float         g_rl1[BB];
__device__ float         g_rl2[NSN];

// ---------------- low-level helpers ------------------------------------------
__device__ __forceinline__ uint32_t smem_u32(const void* p) {
    uint32_t a;
    asm("{ .reg .u64 t; cvta.to.shared.u64 t, %1; cvt.u32.u64 %0, t; }" : "=r"(a) : "l"(p));
    return a;
}
__device__ __forceinline__ void cpasync16(uint32_t dst, const void* src) {
    asm volatile("cp.async.cg.shared.global [%0], [%1], 16;" :: "r"(dst), "l"(src) : "memory");
}
#define CP_COMMIT() asm volatile("cp.async.commit_group;" ::: "memory")
#define CP_WAIT(n)  asm volatile("cp.async.wait_group %0;" :: "n"(n) : "memory")

__device__ __forceinline__ void ldm_x4(uint32_t& r0, uint32_t& r1, uint32_t& r2, uint32_t& r3,
                                       uint32_t addr) {
    asm volatile("ldmatrix.sync.aligned.m8n8.x4.shared.b16 {%0,%1,%2,%3}, [%4];"
                 : "=r"(r0), "=r"(r1), "=r"(r2), "=r"(r3) : "r"(addr));
}
__device__ __forceinline__ void mma16816(float* c, const uint32_t* a, const uint32_t* b) {
    asm volatile(
        "mma.sync.aligned.m16n8k16.row.col.f32.bf16.bf16.f32 "
        "{%0,%1,%2,%3},{%4,%5,%6,%7},{%8,%9},{%0,%1,%2,%3};"
        : "+f"(c[0]), "+f"(c[1]), "+f"(c[2]), "+f"(c[3])
        : "r"(a[0]), "r"(a[1]), "r"(a[2]), "r"(a[3]), "r"(b[0]), "r"(b[1]));
}
// smem byte offset for (row, 16B-chunk c of 4): 64B logical rows, 2 rows/128B line, XOR swizzle
__device__ __forceinline__ uint32_t swz(int row, int c) {
    return (uint32_t)(((row >> 1) << 7) + ((((((row & 1) << 2) | c)) ^ ((row >> 1) & 7)) << 4));
}

// ---------------- block reduction --------------------------------------------
__device__ __forceinline__ float blkRedSum(float v) {
    __shared__ float sh[33];
    int lane = threadIdx.x & 31, w = threadIdx.x >> 5;
    #pragma unroll
    for (int o = 16; o > 0; o >>= 1) v += __shfl_xor_sync(0xffffffffu, v, o);
    if (lane == 0) sh[w] = v;
    __syncthreads();
    int nw = blockDim.x >> 5;
    v = (threadIdx.x < (unsigned)nw) ? sh[threadIdx.x] : 0.f;
    if (w == 0) {
        #pragma unroll
        for (int o = 16; o > 0; o >>= 1) v += __shfl_xor_sync(0xffffffffu, v, o);
        if (lane == 0) sh[32] = v;
    }
    __syncthreads();
    float r = sh[32];
    __syncthreads();
    return r;
}

// =============================================================================
// mma.sync bf16 split GEMM, 512 threads, 16 warps (4x4), BN=128, BK=32, 4 stages.
// PASSES=3: Ahi*Bhi + Ahi*Blo + Alo*Bhi.  PASSES=1: Ahi*Bhi only.
// A: [M, 2K] bf16 (hi|lo) row-major (ldA), B: [N, 2K] same. NT product.
// MODE 0: Cf = scale*D   MODE 1: Cf = D + bias
// MODE 2: relu(D+bias) -> bf16 hi/lo into C2 [r][c], [r][loOff+c]
// =============================================================================
template<int MODE, int BM, int PASSES>
__global__ __launch_bounds__(512, 1)
void gemm_tc(const __nv_bfloat16* __restrict__ A, int ldA,
             const __nv_bfloat16* __restrict__ B, int ldB,
             int K, int Ncols,
             const float* __restrict__ bias, float scale,
             float* __restrict__ Cf, __nv_bfloat16* __restrict__ C2,
             int ldC2, int loOff)
{
    constexpr int BN = 128, STAGES = 4;
    constexpr int WM = BM / 4;               // 64 or 32
    constexpr int WN = 32;
    constexpr int MI = WM / 16;              // 4 or 2
    constexpr int NI = WN / 8;               // 4
    constexpr uint32_t ABYTES = BM * 64;
    constexpr uint32_t BBYTES = BN * 64;
    constexpr uint32_t STAGE = ABYTES + BBYTES;

    extern __shared__ __align__(128) char smraw[];
    const uint32_t sm0 = smem_u32(smraw);

    const int tid  = threadIdx.x;
    const int wid  = tid >> 5;
    const int lane = tid & 31;
    const int wm   = wid >> 2;               // 0..3
    const int wn   = wid & 3;                // 0..3

    const int bm = blockIdx.y * BM;
    const int bn = blockIdx.x * BN;
    const int nc = K >> 5;
    const int total = PASSES * nc;

    float acc[MI][NI][4];
    #pragma unroll
    for (int i = 0; i < MI; i++)
        #pragma unroll
        for (int j = 0; j < NI; j++)
            #pragma unroll
            for (int q = 0; q < 4; q++) acc[i][j][q] = 0.f;

    auto load_stage = [&](int t, int buf) {
        int p = t / nc, cc = t - p * nc;
        long acol = (p == 2 ? (long)K : 0) + (long)cc * 32;
        long bcol = (p == 1 ? (long)K : 0) + (long)cc * 32;
        uint32_t aB = sm0 + buf * STAGE;
        uint32_t bBs = aB + ABYTES;
        #pragma unroll
        for (int i = 0; i < BM * 4 / 512; i++) {
            int u = tid + i * 512; int r = u >> 2, c = u & 3;
            cpasync16(aB + swz(r, c), A + (long)(bm + r) * ldA + acol + c * 8);
        }
        {
            int r = tid >> 2, c = tid & 3;
            cpasync16(bBs + swz(r, c), B + (long)(bn + r) * ldB + bcol + c * 8);
        }
    };

    auto compute_stage = [&](int buf) {
        uint32_t aB = sm0 + buf * STAGE;
        uint32_t bB = aB + ABYTES;
        #pragma unroll
        for (int ks = 0; ks < 2; ks++) {
            uint32_t af[MI][4], bf[NI][2];
            int cch = ks * 2 + (lane >> 4);
            #pragma unroll
            for (int mi = 0; mi < MI; mi++) {
                int r = wm * WM + mi * 16 + (lane & 15);
                ldm_x4(af[mi][0], af[mi][1], af[mi][2], af[mi][3], aB + swz(r, cch));
            }
            #pragma unroll
            for (int nj = 0; nj < NI / 2; nj++) {
                int r = wn * WN + nj * 16 + (lane & 15);
                uint32_t q0, q1, q2, q3;
                ldm_x4(q0, q1, q2, q3, bB + swz(r, cch));
                bf[2 * nj][0] = q0; bf[2 * nj + 1][0] = q1;
                bf[2 * nj][1] = q2; bf[2 * nj + 1][1] = q3;
            }
            #pragma unroll
            for (int mi = 0; mi < MI; mi++)
                #pragma unroll
                for (int ni = 0; ni < NI; ni++)
                    mma16816(acc[mi][ni], af[mi], bf[ni]);
        }
    };

    #pragma unroll
    for (int s = 0; s < STAGES - 1; s++) {
        load_stage(s, s);
        CP_COMMIT();
    }

    for (int t = 0; t < total; t++) {
        CP_WAIT(STAGES - 2);
        __syncthreads();
        if (t + STAGES - 1 < total) {
            load_stage(t + STAGES - 1, (t + STAGES - 1) % STAGES);
            CP_COMMIT();
        }
        compute_stage(t % STAGES);
    }

    #pragma unroll
    for (int mi = 0; mi < MI; mi++) {
        int r0 = bm + wm * WM + mi * 16 + (lane >> 2);
        #pragma unroll
        for (int ni = 0; ni < NI; ni++) {
            int c0 = bn + wn * WN + ni * 8 + 2 * (lane & 3);
            float d0 = acc[mi][ni][0], d1 = acc[mi][ni][1];
            float d2 = acc[mi][ni][2], d3 = acc[mi][ni][3];
            if (MODE == 0) {
                float2 u0 = { d0 * scale, d1 * scale };
                float2 u1 = { d2 * scale, d3 * scale };
                *(float2*)(Cf + (long)r0 * Ncols + c0) = u0;
                *(float2*)(Cf + (long)(r0 + 8) * Ncols + c0) = u1;
            } else if (MODE == 1) {
                float b0 = __ldg(bias + c0), b1 = __ldg(bias + c0 + 1);
                float2 u0 = { d0 + b0, d1 + b1 };
                float2 u1 = { d2 + b0, d3 + b1 };
                *(float2*)(Cf + (long)r0 * Ncols + c0) = u0;
                *(float2*)(Cf + (long)(r0 + 8) * Ncols + c0) = u1;
            } else {
                float b0 = __ldg(bias + c0), b1 = __ldg(bias + c0 + 1);
                float v0 = fmaxf(d0 + b0, 0.f), v1 = fmaxf(d1 + b1, 0.f);
                float v2 = fmaxf(d2 + b0, 0.f), v3 = fmaxf(d3 + b1, 0.f);
                __nv_bfloat16 h0 = __float2bfloat16(v0), h1 = __float2bfloat16(v1);
                __nv_bfloat16 h2 = __float2bfloat16(v2), h3 = __float2bfloat16(v3);
                __nv_bfloat16 l0 = __float2bfloat16(v0 - __bfloat162float(h0));
                __nv_bfloat16 l1 = __float2bfloat16(v1 - __bfloat162float(h1));
                __nv_bfloat16 l2 = __float2bfloat16(v2 - __bfloat162float(h2));
                __nv_bfloat16 l3 = __float2bfloat16(v3 - __bfloat162float(h3));
                __nv_bfloat162 hp0; hp0.x = h0; hp0.y = h1;
                __nv_bfloat162 hp1; hp1.x = h2; hp1.y = h3;
                __nv_bfloat162 lp0; lp0.x = l0; lp0.y = l1;
                __nv_bfloat162 lp1; lp1.x = l2; lp1.y = l3;
                *(__nv_bfloat162*)(C2 + (long)r0 * ldC2 + c0) = hp0;
                *(__nv_bfloat162*)(C2 + (long)(r0 + 8) * ldC2 + c0) = hp1;
                *(__nv_bfloat162*)(C2 + (long)r0 * ldC2 + loOff + c0) = lp0;
                *(__nv_bfloat162*)(C2 + (long)(r0 + 8) * ldC2 + loOff + c0) = lp1;
            }
        }
    }
}

// ---------------- fp32 -> bf16 hi/lo split (layout [R, 2K], hi|lo) -----------
__global__ void cvt_split(const float4* __restrict__ in, __nv_bfloat16* __restrict__ out,
                          int kshift, int n4)
{
    int i = blockIdx.x * blockDim.x + threadIdx.x;
    if (i >= n4) return;
    float4 v = in[i];
    long e = (long)i * 4;
    int K = 1 << kshift;
    long r = e >> kshift;
    int k = (int)(e & (K - 1));
    long base = r * (2L * K) + k;
    float f[4] = {v.x, v.y, v.z, v.w};
    __nv_bfloat16 h[4], l[4];
    #pragma unroll
    for (int j = 0; j < 4; j++) {
        h[j] = __float2bfloat16(f[j]);
        l[j] = __float2bfloat16(f[j] - __bfloat162float(h[j]));
    }
    __nv_bfloat162 p0; p0.x = h[0]; p0.y = h[1];
    __nv_bfloat162 p1; p1.x = h[2]; p1.y = h[3];
    __nv_bfloat162 q0; q0.x = l[0]; q0.y = l[1];
    __nv_bfloat162 q1; q1.x = l[2]; q1.y = l[3];
    *(__nv_bfloat162*)(out + base + 0) = p0;
    *(__nv_bfloat162*)(out + base + 2) = p1;
    *(__nv_bfloat162*)(out + base + K + 0) = q0;
    *(__nv_bfloat162*)(out + base + K + 2) = q1;
}

// ---------------- row-wise L2 normalize + split ------------------------------
__global__ void l2norm_split(const float* __restrict__ in,
                             __nv_bfloat16* __restrict__ out2,
                             float* __restrict__ outf)
{
    int row = blockIdx.x;
    const float4* p = (const float4*)(in + (long)row * EE);
    float4 v = p[threadIdx.x];
    float ss = v.x*v.x + v.y*v.y + v.z*v.z + v.w*v.w;
    float tot = blkRedSum(ss);
    float s = 1.f / fmaxf(sqrtf(tot), 1e-12f);
    v.x *= s; v.y *= s; v.z *= s; v.w *= s;
    if (outf) ((float4*)(outf + (long)row * EE))[threadIdx.x] = v;
    long base = (long)row * (2 * EE) + threadIdx.x * 4;
    float f[4] = {v.x, v.y, v.z, v.w};
    __nv_bfloat16 h[4], l[4];
    #pragma unroll
    for (int j = 0; j < 4; j++) {
        h[j] = __float2bfloat16(f[j]);
        l[j] = __float2bfloat16(f[j] - __bfloat162float(h[j]));
    }
    __nv_bfloat162 p0; p0.x = h[0]; p0.y = h[1];
    __nv_bfloat162 p1; p1.x = h[2]; p1.y = h[3];
    __nv_bfloat162 q0; q0.x = l[0]; q0.y = l[1];
    __nv_bfloat162 q1; q1.x = l[2]; q1.y = l[3];
    *(__nv_bfloat162*)(out2 + base + 0) = p0;
    *(__nv_bfloat162*)(out2 + base + 2) = p1;
    *(__nv_bfloat162*)(out2 + base + EE + 0) = q0;
    *(__nv_bfloat162*)(out2 + base + EE + 2) = q1;
}

// ---------------- per-row argmax (first-index tie-break) ---------------------
__global__ void argmax_rows(const float* __restrict__ S, int cols, int* __restrict__ ind)
{
    int row = blockIdx.x;
    const float* p = S + (long)row * cols;
    float best = -INFINITY; int bi = 0x7fffffff;
    for (int c = threadIdx.x; c < cols; c += blockDim.x) {
        float v = p[c];
        if (v > best) { best = v; bi = c; }
    }
    __shared__ float sv[256];
    __shared__ int   si[256];
    sv[threadIdx.x] = best; si[threadIdx.x] = bi;
    __syncthreads();
    for (int s = 128; s > 0; s >>= 1) {
        if (threadIdx.x < (unsigned)s) {
            float ov = sv[threadIdx.x + s]; int oi = si[threadIdx.x + s];
            if (ov > sv[threadIdx.x] || (ov == sv[threadIdx.x] && oi < si[threadIdx.x])) {
                sv[threadIdx.x] = ov; si[threadIdx.x] = oi;
            }
        }
        __syncthreads();
    }
    if (threadIdx.x == 0) ind[row] = si[0];
}

// ---------------- gathers ----------------------------------------------------
__global__ void gather_out(float* __restrict__ out, const float* __restrict__ ns,
                           const int* __restrict__ ind)
{
    int row = blockIdx.x;
    const float4* p = (const float4*)(ns + (long)ind[row] * EE);
    float4* q = (float4*)(out + (long)row * EE);
    q[threadIdx.x] = p[threadIdx.x];
}
__global__ void gather_rows_bf16(__nv_bfloat16* __restrict__ dst,
                                 const __nv_bfloat16* __restrict__ src,
                                 const int* __restrict__ ind)
{
    int row = blockIdx.x;
    const uint4* s = (const uint4*)(src + (long)ind[row] * (2 * EE));
    uint4* d = (uint4*)(dst + (long)row * (2 * EE));
    d[threadIdx.x] = s[threadIdx.x];
}

// ---------------- fast exp on FMA pipe (x <= ~0.5) ---------------------------
__device__ __forceinline__ float fexp(float x) {
    float y = x * 1.4426950408889634f;
    float m = y + 12582912.0f;
    float i = m - 12582912.0f;
    float r = y - i;
    float p = 9.61812910762848e-3f;
    p = fmaf(p, r, 5.55041086648216e-2f);
    p = fmaf(p, r, 2.40226506959101e-1f);
    p = fmaf(p, r, 6.93147180559945e-1f);
    p = fmaf(p, r, 1.0f);
    int sc = (__float_as_int(m) - 0x4B400000 + 127) << 23;
    return p * __int_as_float(sc);
}

// ---------------- per-row: -log_softmax(softmax(S))[row,row] -----------------
__global__ void row_ce(const float* __restrict__ S, int cols, float* __restrict__ rl)
{
    int row = blockIdx.x;
    const float* p = S + (long)row * cols;
    __shared__ float spd;
    float S1 = 0.f, S2 = 0.f, S3 = 0.f;
    int iter = 0;
    for (int c = threadIdx.x; c < cols; c += blockDim.x, iter++) {
        float s = p[c] - 10.0f;
        float e = (iter & 1) ? fexp(s) : __expf(s);
        if (c == row) spd = e;
        float e2 = e * e;
        S1 += e;
        S2 += e2;
        S3 = fmaf(e2, e, S3);
    }
    S1 = blkRedSum(S1);
    S2 = blkRedSum(S2);
    S3 = blkRedSum(S3);
    if (threadIdx.x == 0) {
        float Z = S1;
        float t = (float)cols + 1.0f + S2 / (2.0f * Z * Z) + S3 / (6.0f * Z * Z * Z);
        float pd = spd / Z;
        rl[row] = -(pd - logf(t));
    }
}

// ---------------- final loss -------------------------------------------------
__global__ void final_loss(float* __restrict__ out, long idx)
{
    float s1 = 0.f;
    for (int i = threadIdx.x; i < BB; i += 1024) s1 += g_rl1[i];
    float s2 = (threadIdx.x < NSN) ? g_rl2[threadIdx.x] : 0.f;
    float v = s1 * (1.0f / (float)BB) + s2 * (1.0f / (float)NSN);
    v = blkRedSum(v);
    if (threadIdx.x == 0) out[idx] = v;
}

// ---------------- launch ------------------------------------------------------
extern "C" void kernel_launch(void* const* d_in, const int* in_sizes, int n_in,
                              void* d_out, int out_size)
{
    const float* x          = (const float*)d_in[0];
    const float* body_W     = (const float*)d_in[1];
    const float* body_b     = (const float*)d_in[2];
    const float* fc_W       = (const float*)d_in[3];
    const float* fc_b       = (const float*)d_in[4];
    const float* abs_states = (const float*)d_in[5];
    float* out = (float*)d_out;

    __nv_bfloat16 *x2, *w1, *w2, *f2, *nz2, *ns2, *cb2;
    float *z, *ns, *scores, *compat, *abssim, *rl1, *rl2;
    int* ind;
    cudaGetSymbolAddress((void**)&x2,  g_x2);
    cudaGetSymbolAddress((void**)&w1,  g_w1);
    cudaGetSymbolAddress((void**)&w2,  g_w2);
    cudaGetSymbolAddress((void**)&f2,  g_f2);
    cudaGetSymbolAddress((void**)&z,   g_z);
    cudaGetSymbolAddress((void**)&nz2, g_nz2);
    cudaGetSymbolAddress((void**)&ns,  g_ns);
    cudaGetSymbolAddress((void**)&ns2, g_ns2);
    cudaGetSymbolAddress((void**)&scores, g_scores);
    cudaGetSymbolAddress((void**)&ind, g_ind);
    cudaGetSymbolAddress((void**)&cb2, g_cb2);
    cudaGetSymbolAddress((void**)&compat, g_compat);
    cudaGetSymbolAddress((void**)&abssim, g_abssim);
    cudaGetSymbolAddress((void**)&rl1, g_rl1);
    cudaGetSymbolAddress((void**)&rl2, g_rl2);

    static cudaStream_t s2 = nullptr;
    static cudaEvent_t evFork = nullptr, evJoin = nullptr;
    if (!s2) {
        cudaStreamCreateWithFlags(&s2, cudaStreamNonBlocking);
        cudaEventCreateWithFlags(&evFork, cudaEventDisableTiming);
        cudaEventCreateWithFlags(&evJoin, cudaEventDisableTiming);
    }

    const int SM256 = 4 * (256 * 64 + 128 * 64);   // 98304
    const int SM128 = 4 * (128 * 64 + 128 * 64);   // 65536
    cudaFuncSetAttribute(gemm_tc<2,256,3>, cudaFuncAttributeMaxDynamicSharedMemorySize, SM256);
    cudaFuncSetAttribute(gemm_tc<0,256,1>, cudaFuncAttributeMaxDynamicSharedMemorySize, SM256);
    cudaFuncSetAttribute(gemm_tc<1,128,3>, cudaFuncAttributeMaxDynamicSharedMemorySize, SM128);
    cudaFuncSetAttribute(gemm_tc<0,128,3>, cudaFuncAttributeMaxDynamicSharedMemorySize, SM128);
    cudaFuncSetAttribute(gemm_tc<0,128,1>, cudaFuncAttributeMaxDynamicSharedMemorySize, SM128);

    // 0) split-convert inputs to bf16 hi/lo
    cvt_split<<<(BB * INF_ / 4 + 255) / 256, 256>>>((const float4*)x, x2, 11, BB * INF_ / 4);
    cvt_split<<<(FEATF * INF_ / 4 + 255) / 256, 256>>>((const float4*)body_W, w1, 11, FEATF * INF_ / 4);
    cvt_split<<<(EE * FEATF / 4 + 255) / 256, 256>>>((const float4*)fc_W, w2, 11, EE * FEATF / 4);

    // 1) feat = relu(x @ body_W^T + b) -> split bf16              [4096, 2048]
    gemm_tc<2,256,3><<<dim3(FEATF / 128, BB / 256), 512, SM256>>>(
        x2, 2 * INF_, w1, 2 * INF_, INF_, FEATF, body_b, 1.f,
        nullptr, f2, 2 * FEATF, FEATF);

    // 2) z = feat @ fc_W^T + b                                    [4096, 512]
    gemm_tc<1,128,3><<<dim3(EE / 128, BB / 128), 512, SM128>>>(
        f2, 2 * FEATF, w2, 2 * FEATF, FEATF, EE, fc_b, 1.f,
        z, nullptr, 0, 0);

    // 3) normalize (+split)
    l2norm_split<<<NSN, 128>>>(abs_states, ns2, ns);
    l2norm_split<<<BB, 128>>>(z, nz2, nullptr);

    // fork: abs_sim branch (loss only, single-pass bf16)
    cudaEventRecord(evFork, 0);
    cudaStreamWaitEvent(s2, evFork, 0);
    gemm_tc<0,128,1><<<dim3(NSN / 128, NSN / 128), 512, SM128, s2>>>(
        ns2, 2 * EE, ns2, 2 * EE, EE, NSN, nullptr, INV_T,
        abssim, nullptr, 0, 0);
    row_ce<<<NSN, 256, 0, s2>>>(abssim, NSN, rl2);
    cudaEventRecord(evJoin, s2);

    // 4) scores = (nz @ ns^T) / T                                 [4096, 1024]
    gemm_tc<0,128,3><<<dim3(NSN / 128, BB / 128), 512, SM128>>>(
        nz2, 2 * EE, ns2, 2 * EE, EE, NSN, nullptr, INV_T,
        scores, nullptr, 0, 0);

    // 5) argmax -> ind ; output abs_state = ns[ind]
    argmax_rows<<<BB, 256>>>(scores, NSN, ind);
    gather_out<<<BB, 128>>>(out, ns, ind);
    gather_rows_bf16<<<BB, 128>>>(cb2, ns2, ind);

    // 6) compatible = (nz @ ns[ind]^T) / T  (loss only, 1-pass)   [4096, 4096]
    gemm_tc<0,256,1><<<dim3(BB / 128, BB / 256), 512, SM256>>>(
        nz2, 2 * EE, cb2, 2 * EE, EE, BB, nullptr, INV_T,
        compat, nullptr, 0, 0);
    row_ce<<<BB, 256>>>(compat, BB, rl1);

    // join + final loss
    cudaStreamWaitEvent(0, evJoin, 0);
    if (out_size > BB * EE) {
        final_loss<<<1, 1024>>>(out, (long)BB * EE);
    }
}

// round 5
// speedup vs baseline: 2.4544x; 1.1892x over previous
#include <cuda_runtime.h>
#include <cuda_bf16.h>
#include <cstdint>
#include <math.h>

#define BB    4096
#define INF_  2048
#define FEATF 2048
#define EE    512
#define NSN   1024
#define INV_T 10.0f

// ---------------- scratch ----------------------------------------------------
__device__ __nv_bfloat16 g_x2 [(size_t)BB   * 2 * INF_ ];
__device__ __nv_bfloat16 g_w1 [(size_t)FEATF* 2 * INF_ ];
__device__ __nv_bfloat16 g_w2 [(size_t)EE   * 2 * FEATF];
__device__ __nv_bfloat16 g_f2 [(size_t)BB   * 2 * FEATF];
__device__ float         g_zsp[(size_t)2 * BB * EE];        // split-K halves
__device__ __nv_bfloat16 g_nz2[(size_t)BB * 2 * EE];
__device__ float         g_ns [(size_t)NSN * EE];
__device__ __nv_bfloat16 g_ns2[(size_t)NSN * 2 * EE];
__device__ __nv_bfloat16 g_cb2[(size_t)BB * 2 * EE];
__device__ unsigned long long g_amax[BB];
__device__ float         g_p1[(size_t)BB * 32 * 3];         // compat CE partials
__device__ float         g_d1[BB];
__device__ float         g_p2[(size_t)NSN * 8 * 3];         // abssim CE partials
__device__ float         g_d2[NSN];
__device__ float         g_rl1[BB];
__device__ float         g_rl2[NSN];

// ---------------- helpers ----------------------------------------------------
__device__ __forceinline__ uint32_t smem_u32(const void* p) {
    uint32_t a;
    asm("{ .reg .u64 t; cvta.to.shared.u64 t, %1; cvt.u32.u64 %0, t; }" : "=r"(a) : "l"(p));
    return a;
}
__device__ __forceinline__ void cpasync16(uint32_t dst, const void* src) {
    asm volatile("cp.async.cg.shared.global [%0], [%1], 16;" :: "r"(dst), "l"(src) : "memory");
}
#define CP_COMMIT() asm volatile("cp.async.commit_group;" ::: "memory")
#define CP_WAIT(n)  asm volatile("cp.async.wait_group %0;" :: "n"(n) : "memory")

__device__ __forceinline__ void ldm_x4(uint32_t& r0, uint32_t& r1, uint32_t& r2, uint32_t& r3,
                                       uint32_t addr) {
    asm volatile("ldmatrix.sync.aligned.m8n8.x4.shared.b16 {%0,%1,%2,%3}, [%4];"
                 : "=r"(r0), "=r"(r1), "=r"(r2), "=r"(r3) : "r"(addr));
}
__device__ __forceinline__ void mma16816(float* c, const uint32_t* a, const uint32_t* b) {
    asm volatile(
        "mma.sync.aligned.m16n8k16.row.col.f32.bf16.bf16.f32 "
        "{%0,%1,%2,%3},{%4,%5,%6,%7},{%8,%9},{%0,%1,%2,%3};"
        : "+f"(c[0]), "+f"(c[1]), "+f"(c[2]), "+f"(c[3])
        : "r"(a[0]), "r"(a[1]), "r"(a[2]), "r"(a[3]), "r"(b[0]), "r"(b[1]));
}
__device__ __forceinline__ uint32_t swz(int row, int c) {
    return (uint32_t)(((row >> 1) << 7) + ((((((row & 1) << 2) | c)) ^ ((row >> 1) & 7)) << 4));
}
__device__ __forceinline__ unsigned long long packkey(float v, int col) {
    uint32_t u = __float_as_uint(v);
    u = (u & 0x80000000u) ? ~u : (u | 0x80000000u);
    return ((unsigned long long)u << 32) | (uint32_t)(~col);
}

__device__ __forceinline__ float blkRedSum(float v) {
    __shared__ float sh[33];
    int lane = threadIdx.x & 31, w = threadIdx.x >> 5;
    #pragma unroll
    for (int o = 16; o > 0; o >>= 1) v += __shfl_xor_sync(0xffffffffu, v, o);
    if (lane == 0) sh[w] = v;
    __syncthreads();
    int nw = blockDim.x >> 5;
    v = (threadIdx.x < (unsigned)nw) ? sh[threadIdx.x] : 0.f;
    if (w == 0) {
        #pragma unroll
        for (int o = 16; o > 0; o >>= 1) v += __shfl_xor_sync(0xffffffffu, v, o);
        if (lane == 0) sh[32] = v;
    }
    __syncthreads();
    float r = sh[32];
    __syncthreads();
    return r;
}

// =============================================================================
// bf16 split GEMM, 256 threads (8 warps 4x2), BM=BN=128, BK=32, 4 stages.
// PASSES=3: Ahi*Bhi + Ahi*Blo + Alo*Bhi. PASSES=1: hi only. SPLITK via blockIdx.z.
// MODE 0: Cf[z*zstride + r*Ncols + c] = scale*D
// MODE 2: relu(D + bias) -> bf16 hi/lo into C2
// MODE 3: fused CE: e=exp(D*scale-10); per-row (S1,S2,S3) -> P[(r*nbx+bx)*3+s]; diag -> Dg
// MODE 4: fused argmax: atomicMax(amax[r], pack(D, c))
// =============================================================================
template<int MODE, int PASSES, int SPLITK>
__global__ __launch_bounds__(256, 2)
void gemm_k(const __nv_bfloat16* __restrict__ A, int ldA,
            const __nv_bfloat16* __restrict__ B, int ldB,
            int K, int Ncols,
            const float* __restrict__ bias, float scale,
            float* __restrict__ Cf, size_t zstride,
            __nv_bfloat16* __restrict__ C2, int ldC2, int loOff,
            float* __restrict__ P, int nbx, float* __restrict__ Dg,
            unsigned long long* __restrict__ amax)
{
    constexpr int STAGES = 4;
    constexpr int MI = 2, NI = 8;            // warp tile 32x64
    constexpr uint32_t STAGE = 16384;        // (128+128) rows * 64B

    extern __shared__ __align__(128) char smraw[];
    const uint32_t sm0 = smem_u32(smraw);

    const int tid  = threadIdx.x;
    const int wid  = tid >> 5;
    const int lane = tid & 31;
    const int wm   = wid >> 1;               // 0..3
    const int wn   = wid & 1;                // 0..1

    const int bm = blockIdx.y * 128;
    const int bn = blockIdx.x * 128;
    const int nc = K >> 5;
    const int half = nc / SPLITK;
    const int zid = (SPLITK > 1) ? blockIdx.z : 0;
    const int total = PASSES * half;

    float acc[MI][NI][4];
    #pragma unroll
    for (int i = 0; i < MI; i++)
        #pragma unroll
        for (int j = 0; j < NI; j++)
            #pragma unroll
            for (int q = 0; q < 4; q++) acc[i][j][q] = 0.f;

    auto load_stage = [&](int t, int buf) {
        int p = t / half, cc = zid * half + (t - p * half);
        long acol = (p == 2 ? (long)K : 0) + (long)cc * 32;
        long bcol = (p == 1 ? (long)K : 0) + (long)cc * 32;
        uint32_t aB = sm0 + buf * STAGE;
        uint32_t bBs = aB + 8192;
        #pragma unroll
        for (int i = 0; i < 2; i++) {
            int u = tid + i * 256; int r = u >> 2, c = u & 3;
            cpasync16(aB + swz(r, c), A + (long)(bm + r) * ldA + acol + c * 8);
        }
        #pragma unroll
        for (int i = 0; i < 2; i++) {
            int u = tid + i * 256; int r = u >> 2, c = u & 3;
            cpasync16(bBs + swz(r, c), B + (long)(bn + r) * ldB + bcol + c * 8);
        }
    };

    auto compute_stage = [&](int buf) {
        uint32_t aB = sm0 + buf * STAGE;
        uint32_t bB = aB + 8192;
        #pragma unroll
        for (int ks = 0; ks < 2; ks++) {
            uint32_t af[MI][4], bf[NI][2];
            int cch = ks * 2 + (lane >> 4);
            #pragma unroll
            for (int mi = 0; mi < MI; mi++) {
                int r = wm * 32 + mi * 16 + (lane & 15);
                ldm_x4(af[mi][0], af[mi][1], af[mi][2], af[mi][3], aB + swz(r, cch));
            }
            #pragma unroll
            for (int nj = 0; nj < NI / 2; nj++) {
                int r = wn * 64 + nj * 16 + (lane & 15);
                uint32_t q0, q1, q2, q3;
                ldm_x4(q0, q1, q2, q3, bB + swz(r, cch));
                bf[2 * nj][0] = q0; bf[2 * nj + 1][0] = q1;
                bf[2 * nj][1] = q2; bf[2 * nj + 1][1] = q3;
            }
            #pragma unroll
            for (int mi = 0; mi < MI; mi++)
                #pragma unroll
                for (int ni = 0; ni < NI; ni++)
                    mma16816(acc[mi][ni], af[mi], bf[ni]);
        }
    };

    #pragma unroll
    for (int s = 0; s < STAGES - 1; s++) { load_stage(s, s); CP_COMMIT(); }

    for (int t = 0; t < total; t++) {
        CP_WAIT(STAGES - 2);
        __syncthreads();
        if (t + STAGES - 1 < total) {
            load_stage(t + STAGES - 1, (t + STAGES - 1) % STAGES);
            CP_COMMIT();
        }
        compute_stage(t % STAGES);
    }

    if (MODE == 3) {
        float S[MI][2][3];
        #pragma unroll
        for (int mi = 0; mi < MI; mi++)
            #pragma unroll
            for (int h = 0; h < 2; h++)
                #pragma unroll
                for (int s = 0; s < 3; s++) S[mi][h][s] = 0.f;
        #pragma unroll
        for (int mi = 0; mi < MI; mi++) {
            int r0 = bm + wm * 32 + mi * 16 + (lane >> 2);
            #pragma unroll
            for (int ni = 0; ni < NI; ni++) {
                int c0 = bn + wn * 64 + ni * 8 + 2 * (lane & 3);
                #pragma unroll
                for (int q = 0; q < 4; q++) {
                    int gr = r0 + (q >> 1) * 8;
                    int gc = c0 + (q & 1);
                    float e = __expf(fmaf(acc[mi][ni][q], scale, -10.f));
                    if (gr == gc) Dg[gr] = e;
                    float e2 = e * e;
                    S[mi][q >> 1][0] += e;
                    S[mi][q >> 1][1] += e2;
                    S[mi][q >> 1][2] = fmaf(e2, e, S[mi][q >> 1][2]);
                }
            }
        }
        #pragma unroll
        for (int mi = 0; mi < MI; mi++)
            #pragma unroll
            for (int h = 0; h < 2; h++)
                #pragma unroll
                for (int s = 0; s < 3; s++) {
                    float v = S[mi][h][s];
                    v += __shfl_xor_sync(0xffffffffu, v, 1);
                    v += __shfl_xor_sync(0xffffffffu, v, 2);
                    S[mi][h][s] = v;
                }
        __syncthreads();                         // pipeline smem done; reuse
        float* sums = (float*)smraw;             // [2][128][3]
        if ((lane & 3) == 0) {
            #pragma unroll
            for (int mi = 0; mi < MI; mi++)
                #pragma unroll
                for (int h = 0; h < 2; h++) {
                    int rib = wm * 32 + mi * 16 + (lane >> 2) + h * 8;
                    #pragma unroll
                    for (int s = 0; s < 3; s++)
                        sums[(wn * 128 + rib) * 3 + s] = S[mi][h][s];
                }
        }
        __syncthreads();
        if (tid < 128) {
            #pragma unroll
            for (int s = 0; s < 3; s++)
                P[((size_t)(bm + tid) * nbx + blockIdx.x) * 3 + s] =
                    sums[tid * 3 + s] + sums[(128 + tid) * 3 + s];
        }
        return;
    }

    if (MODE == 4) {
        #pragma unroll
        for (int mi = 0; mi < MI; mi++) {
            int r0 = bm + wm * 32 + mi * 16 + (lane >> 2);
            #pragma unroll
            for (int h = 0; h < 2; h++) {
                unsigned long long key = 0;
                #pragma unroll
                for (int ni = 0; ni < NI; ni++) {
                    int c0 = bn + wn * 64 + ni * 8 + 2 * (lane & 3);
                    unsigned long long k0 = packkey(acc[mi][ni][h * 2 + 0], c0);
                    unsigned long long k1 = packkey(acc[mi][ni][h * 2 + 1], c0 + 1);
                    if (k0 > key) key = k0;
                    if (k1 > key) key = k1;
                }
                #pragma unroll
                for (int o = 1; o <= 2; o <<= 1) {
                    unsigned long long ok = __shfl_xor_sync(0xffffffffu, key, o);
                    if (ok > key) key = ok;
                }
                if ((lane & 3) == 0) atomicMax(amax + r0 + h * 8, key);
            }
        }
        return;
    }

    #pragma unroll
    for (int mi = 0; mi < MI; mi++) {
        int r0 = bm + wm * 32 + mi * 16 + (lane >> 2);
        #pragma unroll
        for (int ni = 0; ni < NI; ni++) {
            int c0 = bn + wn * 64 + ni * 8 + 2 * (lane & 3);
            float d0 = acc[mi][ni][0], d1 = acc[mi][ni][1];
            float d2 = acc[mi][ni][2], d3 = acc[mi][ni][3];
            if (MODE == 0) {
                float* o = Cf + (size_t)zid * zstride;
                float2 u0 = { d0 * scale, d1 * scale };
                float2 u1 = { d2 * scale, d3 * scale };
                *(float2*)(o + (long)r0 * Ncols + c0) = u0;
                *(float2*)(o + (long)(r0 + 8) * Ncols + c0) = u1;
            } else if (MODE == 2) {
                float b0 = __ldg(bias + c0), b1 = __ldg(bias + c0 + 1);
                float v0 = fmaxf(d0 + b0, 0.f), v1 = fmaxf(d1 + b1, 0.f);
                float v2 = fmaxf(d2 + b0, 0.f), v3 = fmaxf(d3 + b1, 0.f);
                __nv_bfloat16 h0 = __float2bfloat16(v0), h1 = __float2bfloat16(v1);
                __nv_bfloat16 h2 = __float2bfloat16(v2), h3 = __float2bfloat16(v3);
                __nv_bfloat16 l0 = __float2bfloat16(v0 - __bfloat162float(h0));
                __nv_bfloat16 l1 = __float2bfloat16(v1 - __bfloat162float(h1));
                __nv_bfloat16 l2 = __float2bfloat16(v2 - __bfloat162float(h2));
                __nv_bfloat16 l3 = __float2bfloat16(v3 - __bfloat162float(h3));
                __nv_bfloat162 hp0; hp0.x = h0; hp0.y = h1;
                __nv_bfloat162 hp1; hp1.x = h2; hp1.y = h3;
                __nv_bfloat162 lp0; lp0.x = l0; lp0.y = l1;
                __nv_bfloat162 lp1; lp1.x = l2; lp1.y = l3;
                *(__nv_bfloat162*)(C2 + (long)r0 * ldC2 + c0) = hp0;
                *(__nv_bfloat162*)(C2 + (long)(r0 + 8) * ldC2 + c0) = hp1;
                *(__nv_bfloat162*)(C2 + (long)r0 * ldC2 + loOff + c0) = lp0;
                *(__nv_bfloat162*)(C2 + (long)(r0 + 8) * ldC2 + loOff + c0) = lp1;
            }
        }
    }
}

// ---------------- fp32 -> bf16 hi/lo split -----------------------------------
__global__ void cvt_split(const float4* __restrict__ in, __nv_bfloat16* __restrict__ out,
                          int kshift, int n4)
{
    int i = blockIdx.x * blockDim.x + threadIdx.x;
    if (i >= n4) return;
    float4 v = in[i];
    long e = (long)i * 4;
    int K = 1 << kshift;
    long r = e >> kshift;
    int k = (int)(e & (K - 1));
    long base = r * (2L * K) + k;
    float f[4] = {v.x, v.y, v.z, v.w};
    __nv_bfloat16 h[4], l[4];
    #pragma unroll
    for (int j = 0; j < 4; j++) {
        h[j] = __float2bfloat16(f[j]);
        l[j] = __float2bfloat16(f[j] - __bfloat162float(h[j]));
    }
    __nv_bfloat162 p0; p0.x = h[0]; p0.y = h[1];
    __nv_bfloat162 p1; p1.x = h[2]; p1.y = h[3];
    __nv_bfloat162 q0; q0.x = l[0]; q0.y = l[1];
    __nv_bfloat162 q1; q1.x = l[2]; q1.y = l[3];
    *(__nv_bfloat162*)(out + base + 0) = p0;
    *(__nv_bfloat162*)(out + base + 2) = p1;
    *(__nv_bfloat162*)(out + base + K + 0) = q0;
    *(__nv_bfloat162*)(out + base + K + 2) = q1;
}

// ---------------- l2 normalize + split (abs_states; also fp32 out) -----------
__global__ void l2norm_split(const float* __restrict__ in,
                             __nv_bfloat16* __restrict__ out2,
                             float* __restrict__ outf)
{
    int row = blockIdx.x;
    const float4* p = (const float4*)(in + (long)row * EE);
    float4 v = p[threadIdx.x];
    float ss = v.x*v.x + v.y*v.y + v.z*v.z + v.w*v.w;
    float tot = blkRedSum(ss);
    float s = 1.f / fmaxf(sqrtf(tot), 1e-12f);
    v.x *= s; v.y *= s; v.z *= s; v.w *= s;
    if (outf) ((float4*)(outf + (long)row * EE))[threadIdx.x] = v;
    long base = (long)row * (2 * EE) + threadIdx.x * 4;
    float f[4] = {v.x, v.y, v.z, v.w};
    __nv_bfloat16 h[4], l[4];
    #pragma unroll
    for (int j = 0; j < 4; j++) {
        h[j] = __float2bfloat16(f[j]);
        l[j] = __float2bfloat16(f[j] - __bfloat162float(h[j]));
    }
    __nv_bfloat162 p0; p0.x = h[0]; p0.y = h[1];
    __nv_bfloat162 p1; p1.x = h[2]; p1.y = h[3];
    __nv_bfloat162 q0; q0.x = l[0]; q0.y = l[1];
    __nv_bfloat162 q1; q1.x = l[2]; q1.y = l[3];
    *(__nv_bfloat162*)(out2 + base + 0) = p0;
    *(__nv_bfloat162*)(out2 + base + 2) = p1;
    *(__nv_bfloat162*)(out2 + base + EE + 0) = q0;
    *(__nv_bfloat162*)(out2 + base + EE + 2) = q1;
}

// ---------------- merge split-K halves + bias, normalize, split --------------
__global__ void l2norm_merge(const float* __restrict__ za, const float* __restrict__ zb,
                             const float* __restrict__ bias,
                             __nv_bfloat16* __restrict__ out2)
{
    int row = blockIdx.x;
    float4 a = ((const float4*)(za + (long)row * EE))[threadIdx.x];
    float4 b = ((const float4*)(zb + (long)row * EE))[threadIdx.x];
    float4 c = ((const float4*)bias)[threadIdx.x];
    float4 v = { a.x + b.x + c.x, a.y + b.y + c.y, a.z + b.z + c.z, a.w + b.w + c.w };
    float ss = v.x*v.x + v.y*v.y + v.z*v.z + v.w*v.w;
    float tot = blkRedSum(ss);
    float s = 1.f / fmaxf(sqrtf(tot), 1e-12f);
    v.x *= s; v.y *= s; v.z *= s; v.w *= s;
    long base = (long)row * (2 * EE) + threadIdx.x * 4;
    float f[4] = {v.x, v.y, v.z, v.w};
    __nv_bfloat16 h[4], l[4];
    #pragma unroll
    for (int j = 0; j < 4; j++) {
        h[j] = __float2bfloat16(f[j]);
        l[j] = __float2bfloat16(f[j] - __bfloat162float(h[j]));
    }
    __nv_bfloat162 p0; p0.x = h[0]; p0.y = h[1];
    __nv_bfloat162 p1; p1.x = h[2]; p1.y = h[3];
    __nv_bfloat162 q0; q0.x = l[0]; q0.y = l[1];
    __nv_bfloat162 q1; q1.x = l[2]; q1.y = l[3];
    *(__nv_bfloat162*)(out2 + base + 0) = p0;
    *(__nv_bfloat162*)(out2 + base + 2) = p1;
    *(__nv_bfloat162*)(out2 + base + EE + 0) = q0;
    *(__nv_bfloat162*)(out2 + base + EE + 2) = q1;
}

// ---------------- init amax --------------------------------------------------
__global__ void init_amax(unsigned long long* a, int n)
{
    int i = blockIdx.x * blockDim.x + threadIdx.x;
    if (i < n) a[i] = 0ull;
}

// ---------------- decode argmax, gather output + compat B --------------------
__global__ void gather_all(float* __restrict__ out, __nv_bfloat16* __restrict__ cb2,
                           const float* __restrict__ ns, const __nv_bfloat16* __restrict__ ns2,
                           const unsigned long long* __restrict__ amax)
{
    int row = blockIdx.x;
    int idx = (int)(~(uint32_t)(amax[row] & 0xffffffffull));
    ((float4*)(out + (long)row * EE))[threadIdx.x] =
        ((const float4*)(ns + (long)idx * EE))[threadIdx.x];
    ((uint4*)(cb2 + (long)row * (2 * EE)))[threadIdx.x] =
        ((const uint4*)(ns2 + (long)idx * (2 * EE)))[threadIdx.x];
}

// ---------------- CE finish: fixed-order reduce of partials ------------------
__global__ void ce_finish(const float* __restrict__ P, int nbx,
                          const float* __restrict__ Dg, int cols,
                          float* __restrict__ rl, int rows)
{
    int r = blockIdx.x * blockDim.x + threadIdx.x;
    if (r >= rows) return;
    float S1 = 0.f, S2 = 0.f, S3 = 0.f;
    const float* p = P + (size_t)r * nbx * 3;
    for (int b = 0; b < nbx; b++) {
        S1 += p[b * 3 + 0];
        S2 += p[b * 3 + 1];
        S3 += p[b * 3 + 2];
    }
    float Z = S1;
    float t = (float)cols + 1.0f + S2 / (2.0f * Z * Z) + S3 / (6.0f * Z * Z * Z);
    float pd = Dg[r] / Z;
    rl[r] = -(pd - logf(t));
}

// ---------------- final loss -------------------------------------------------
__global__ void final_loss(float* __restrict__ out, long idx)
{
    float s1 = 0.f;
    for (int i = threadIdx.x; i < BB; i += 1024) s1 += g_rl1[i];
    float s2 = (threadIdx.x < NSN) ? g_rl2[threadIdx.x] : 0.f;
    float v = s1 * (1.0f / (float)BB) + s2 * (1.0f / (float)NSN);
    v = blkRedSum(v);
    if (threadIdx.x == 0) out[idx] = v;
}

// ---------------- launch ------------------------------------------------------
extern "C" void kernel_launch(void* const* d_in, const int* in_sizes, int n_in,
                              void* d_out, int out_size)
{
    const float* x          = (const float*)d_in[0];
    const float* body_W     = (const float*)d_in[1];
    const float* body_b     = (const float*)d_in[2];
    const float* fc_W       = (const float*)d_in[3];
    const float* fc_b       = (const float*)d_in[4];
    const float* abs_states = (const float*)d_in[5];
    float* out = (float*)d_out;

    __nv_bfloat16 *x2, *w1, *w2, *f2, *nz2, *ns2, *cb2;
    float *zsp, *ns, *p1, *d1, *p2, *d2, *rl1, *rl2;
    unsigned long long* amax;
    cudaGetSymbolAddress((void**)&x2,  g_x2);
    cudaGetSymbolAddress((void**)&w1,  g_w1);
    cudaGetSymbolAddress((void**)&w2,  g_w2);
    cudaGetSymbolAddress((void**)&f2,  g_f2);
    cudaGetSymbolAddress((void**)&zsp, g_zsp);
    cudaGetSymbolAddress((void**)&nz2, g_nz2);
    cudaGetSymbolAddress((void**)&ns,  g_ns);
    cudaGetSymbolAddress((void**)&ns2, g_ns2);
    cudaGetSymbolAddress((void**)&cb2, g_cb2);
    cudaGetSymbolAddress((void**)&amax, g_amax);
    cudaGetSymbolAddress((void**)&p1,  g_p1);
    cudaGetSymbolAddress((void**)&d1,  g_d1);
    cudaGetSymbolAddress((void**)&p2,  g_p2);
    cudaGetSymbolAddress((void**)&d2,  g_d2);
    cudaGetSymbolAddress((void**)&rl1, g_rl1);
    cudaGetSymbolAddress((void**)&rl2, g_rl2);

    static cudaStream_t s2 = nullptr;
    static cudaEvent_t eNS = nullptr, eW2 = nullptr, e1 = nullptr;
    if (!s2) {
        cudaStreamCreateWithFlags(&s2, cudaStreamNonBlocking);
        cudaEventCreateWithFlags(&eNS, cudaEventDisableTiming);
        cudaEventCreateWithFlags(&eW2, cudaEventDisableTiming);
        cudaEventCreateWithFlags(&e1, cudaEventDisableTiming);
    }

    const int SMEMB = 65536;
    cudaFuncSetAttribute(gemm_k<2,3,1>, cudaFuncAttributeMaxDynamicSharedMemorySize, SMEMB);
    cudaFuncSetAttribute(gemm_k<0,3,2>, cudaFuncAttributeMaxDynamicSharedMemorySize, SMEMB);
    cudaFuncSetAttribute(gemm_k<4,3,1>, cudaFuncAttributeMaxDynamicSharedMemorySize, SMEMB);
    cudaFuncSetAttribute(gemm_k<3,1,1>, cudaFuncAttributeMaxDynamicSharedMemorySize, SMEMB);

    // main: conversions + abs_states normalize
    init_amax<<<(BB + 255) / 256, 256>>>(amax, BB);
    cvt_split<<<(BB * INF_ / 4 + 255) / 256, 256>>>((const float4*)x, x2, 11, BB * INF_ / 4);
    cvt_split<<<(FEATF * INF_ / 4 + 255) / 256, 256>>>((const float4*)body_W, w1, 11, FEATF * INF_ / 4);
    l2norm_split<<<NSN, 128>>>(abs_states, ns2, ns);
    cudaEventRecord(eNS, 0);

    // s2: fc_W conversion + abssim CE branch (overlaps GEMM1)
    cudaStreamWaitEvent(s2, eNS, 0);
    cvt_split<<<(EE * FEATF / 4 + 255) / 256, 256, 0, s2>>>((const float4*)fc_W, w2, 11, EE * FEATF / 4);
    cudaEventRecord(eW2, s2);
    gemm_k<3,1,1><<<dim3(NSN / 128, NSN / 128), 256, SMEMB, s2>>>(
        ns2, 2 * EE, ns2, 2 * EE, EE, NSN, nullptr, INV_T,
        nullptr, 0, nullptr, 0, 0, p2, 8, d2, nullptr);
    ce_finish<<<(NSN + 255) / 256, 256, 0, s2>>>(p2, 8, d2, NSN, rl2, NSN);
    cudaEventRecord(e1, s2);

    // 1) feat = relu(x @ body_W^T + b) -> split bf16
    gemm_k<2,3,1><<<dim3(FEATF / 128, BB / 128), 256, SMEMB>>>(
        x2, 2 * INF_, w1, 2 * INF_, INF_, FEATF, body_b, 1.f,
        nullptr, 0, f2, 2 * FEATF, FEATF, nullptr, 0, nullptr, nullptr);

    // 2) z = feat @ fc_W^T (split-K=2)
    cudaStreamWaitEvent(0, eW2, 0);
    gemm_k<0,3,2><<<dim3(EE / 128, BB / 128, 2), 256, SMEMB>>>(
        f2, 2 * FEATF, w2, 2 * FEATF, FEATF, EE, nullptr, 1.f,
        zsp, (size_t)BB * EE, nullptr, 0, 0, nullptr, 0, nullptr, nullptr);

    // 3) merge halves + fc_b, normalize, split
    l2norm_merge<<<BB, 128>>>(zsp, zsp + (size_t)BB * EE, fc_b, nz2);

    // 4) scores + fused argmax
    gemm_k<4,3,1><<<dim3(NSN / 128, BB / 128), 256, SMEMB>>>(
        nz2, 2 * EE, ns2, 2 * EE, EE, NSN, nullptr, 1.f,
        nullptr, 0, nullptr, 0, 0, nullptr, 0, nullptr, amax);

    // 5) gather output + compat B operand
    gather_all<<<BB, 128>>>(out, cb2, ns, ns2, amax);

    // 6) compat + fused CE
    gemm_k<3,1,1><<<dim3(BB / 128, BB / 128), 256, SMEMB>>>(
        nz2, 2 * EE, cb2, 2 * EE, EE, BB, nullptr, INV_T,
        nullptr, 0, nullptr, 0, 0, p1, 32, d1, nullptr);
    ce_finish<<<(BB + 255) / 256, 256>>>(p1, 32, d1, BB, rl1, BB);

    // join + final loss
    cudaStreamWaitEvent(0, e1, 0);
    if (out_size > BB * EE) {
        final_loss<<<1, 1024>>>(out, (long)BB * EE);
    }
}

// round 6
// speedup vs baseline: 2.7444x; 1.1182x over previous
#include <cuda_runtime.h>
#include <cuda_bf16.h>
#include <cstdint>
#include <math.h>

#define BB    4096
#define INF_  2048
#define FEATF 2048
#define EE    512
#define NSN   1024
#define INV_T 10.0f

// ---------------- scratch ----------------------------------------------------
__device__ __nv_bfloat16 g_x2 [(size_t)BB   * 2 * INF_ ];
__device__ __nv_bfloat16 g_w1 [(size_t)FEATF* 2 * INF_ ];
__device__ __nv_bfloat16 g_w2 [(size_t)EE   * 2 * FEATF];
__device__ __nv_bfloat16 g_f2 [(size_t)BB   * 2 * FEATF];
__device__ float         g_zsp[(size_t)2 * BB * EE];        // split-K halves
__device__ __nv_bfloat16 g_nz2[(size_t)BB * 2 * EE];
__device__ float         g_ns [(size_t)NSN * EE];
__device__ __nv_bfloat16 g_ns2[(size_t)NSN * 2 * EE];
__device__ float         g_scores[(size_t)BB * NSN];        // raw cosine dots
__device__ unsigned long long g_amax[BB];
__device__ int           g_cnt[NSN];
__device__ float         g_p2[(size_t)NSN * 8 * 3];         // abssim CE partials
__device__ float         g_d2[NSN];
__device__ float         g_rl1[BB];
__device__ float         g_rl2[NSN];

// ---------------- helpers ----------------------------------------------------
__device__ __forceinline__ uint32_t smem_u32(const void* p) {
    uint32_t a;
    asm("{ .reg .u64 t; cvta.to.shared.u64 t, %1; cvt.u32.u64 %0, t; }" : "=r"(a) : "l"(p));
    return a;
}
__device__ __forceinline__ void cpasync16(uint32_t dst, const void* src) {
    asm volatile("cp.async.cg.shared.global [%0], [%1], 16;" :: "r"(dst), "l"(src) : "memory");
}
#define CP_COMMIT() asm volatile("cp.async.commit_group;" ::: "memory")
#define CP_WAIT(n)  asm volatile("cp.async.wait_group %0;" :: "n"(n) : "memory")

__device__ __forceinline__ void ldm_x4(uint32_t& r0, uint32_t& r1, uint32_t& r2, uint32_t& r3,
                                       uint32_t addr) {
    asm volatile("ldmatrix.sync.aligned.m8n8.x4.shared.b16 {%0,%1,%2,%3}, [%4];"
                 : "=r"(r0), "=r"(r1), "=r"(r2), "=r"(r3) : "r"(addr));
}
__device__ __forceinline__ void mma16816(float* c, const uint32_t* a, const uint32_t* b) {
    asm volatile(
        "mma.sync.aligned.m16n8k16.row.col.f32.bf16.bf16.f32 "
        "{%0,%1,%2,%3},{%4,%5,%6,%7},{%8,%9},{%0,%1,%2,%3};"
        : "+f"(c[0]), "+f"(c[1]), "+f"(c[2]), "+f"(c[3])
        : "r"(a[0]), "r"(a[1]), "r"(a[2]), "r"(a[3]), "r"(b[0]), "r"(b[1]));
}
__device__ __forceinline__ uint32_t swz(int row, int c) {
    return (uint32_t)(((row >> 1) << 7) + ((((((row & 1) << 2) | c)) ^ ((row >> 1) & 7)) << 4));
}
__device__ __forceinline__ unsigned long long packkey(float v, int col) {
    uint32_t u = __float_as_uint(v);
    u = (u & 0x80000000u) ? ~u : (u | 0x80000000u);
    return ((unsigned long long)u << 32) | (uint32_t)(~col);
}

__device__ __forceinline__ float blkRedSum(float v) {
    __shared__ float sh[33];
    int lane = threadIdx.x & 31, w = threadIdx.x >> 5;
    #pragma unroll
    for (int o = 16; o > 0; o >>= 1) v += __shfl_xor_sync(0xffffffffu, v, o);
    if (lane == 0) sh[w] = v;
    __syncthreads();
    int nw = blockDim.x >> 5;
    v = (threadIdx.x < (unsigned)nw) ? sh[threadIdx.x] : 0.f;
    if (w == 0) {
        #pragma unroll
        for (int o = 16; o > 0; o >>= 1) v += __shfl_xor_sync(0xffffffffu, v, o);
        if (lane == 0) sh[32] = v;
    }
    __syncthreads();
    float r = sh[32];
    __syncthreads();
    return r;
}

// ---------------- fast exp on FMA pipe ---------------------------------------
__device__ __forceinline__ float fexp(float x) {
    float y = x * 1.4426950408889634f;
    float m = y + 12582912.0f;
    float i = m - 12582912.0f;
    float r = y - i;
    float p = 9.61812910762848e-3f;
    p = fmaf(p, r, 5.55041086648216e-2f);
    p = fmaf(p, r, 2.40226506959101e-1f);
    p = fmaf(p, r, 6.93147180559945e-1f);
    p = fmaf(p, r, 1.0f);
    int sc = (__float_as_int(m) - 0x4B400000 + 127) << 23;
    return p * __int_as_float(sc);
}

// =============================================================================
// bf16 split GEMM, 256 threads (8 warps 4x2), BM=BN=128, BK=32, 4 stages.
// PASSES=3: Ahi*Bhi + Ahi*Blo + Alo*Bhi. PASSES=1: hi only. SPLITK via blockIdx.z.
// MODE 0: Cf[z*zstride + ...] = scale*D
// MODE 2: relu(D + bias) -> bf16 hi/lo into C2
// MODE 3: fused CE: e=exp(D*scale-10); per-row (S1,S2,S3) -> P; diag -> Dg
// MODE 4: store raw D to Cf AND fused argmax atomicMax(amax[r], pack(D, c))
// =============================================================================
template<int MODE, int PASSES, int SPLITK>
__global__ __launch_bounds__(256, 2)
void gemm_k(const __nv_bfloat16* __restrict__ A, int ldA,
            const __nv_bfloat16* __restrict__ B, int ldB,
            int K, int Ncols,
            const float* __restrict__ bias, float scale,
            float* __restrict__ Cf, size_t zstride,
            __nv_bfloat16* __restrict__ C2, int ldC2, int loOff,
            float* __restrict__ P, int nbx, float* __restrict__ Dg,
            unsigned long long* __restrict__ amax)
{
    constexpr int STAGES = 4;
    constexpr int MI = 2, NI = 8;            // warp tile 32x64
    constexpr uint32_t STAGE = 16384;

    extern __shared__ __align__(128) char smraw[];
    const uint32_t sm0 = smem_u32(smraw);

    const int tid  = threadIdx.x;
    const int wid  = tid >> 5;
    const int lane = tid & 31;
    const int wm   = wid >> 1;
    const int wn   = wid & 1;

    const int bm = blockIdx.y * 128;
    const int bn = blockIdx.x * 128;
    const int nc = K >> 5;
    const int half = nc / SPLITK;
    const int zid = (SPLITK > 1) ? blockIdx.z : 0;
    const int total = PASSES * half;

    float acc[MI][NI][4];
    #pragma unroll
    for (int i = 0; i < MI; i++)
        #pragma unroll
        for (int j = 0; j < NI; j++)
            #pragma unroll
            for (int q = 0; q < 4; q++) acc[i][j][q] = 0.f;

    auto load_stage = [&](int t, int buf) {
        int p = t / half, cc = zid * half + (t - p * half);
        long acol = (p == 2 ? (long)K : 0) + (long)cc * 32;
        long bcol = (p == 1 ? (long)K : 0) + (long)cc * 32;
        uint32_t aB = sm0 + buf * STAGE;
        uint32_t bBs = aB + 8192;
        #pragma unroll
        for (int i = 0; i < 2; i++) {
            int u = tid + i * 256; int r = u >> 2, c = u & 3;
            cpasync16(aB + swz(r, c), A + (long)(bm + r) * ldA + acol + c * 8);
        }
        #pragma unroll
        for (int i = 0; i < 2; i++) {
            int u = tid + i * 256; int r = u >> 2, c = u & 3;
            cpasync16(bBs + swz(r, c), B + (long)(bn + r) * ldB + bcol + c * 8);
        }
    };

    auto compute_stage = [&](int buf) {
        uint32_t aB = sm0 + buf * STAGE;
        uint32_t bB = aB + 8192;
        #pragma unroll
        for (int ks = 0; ks < 2; ks++) {
            uint32_t af[MI][4], bf[NI][2];
            int cch = ks * 2 + (lane >> 4);
            #pragma unroll
            for (int mi = 0; mi < MI; mi++) {
                int r = wm * 32 + mi * 16 + (lane & 15);
                ldm_x4(af[mi][0], af[mi][1], af[mi][2], af[mi][3], aB + swz(r, cch));
            }
            #pragma unroll
            for (int nj = 0; nj < NI / 2; nj++) {
                int r = wn * 64 + nj * 16 + (lane & 15);
                uint32_t q0, q1, q2, q3;
                ldm_x4(q0, q1, q2, q3, bB + swz(r, cch));
                bf[2 * nj][0] = q0; bf[2 * nj + 1][0] = q1;
                bf[2 * nj][1] = q2; bf[2 * nj + 1][1] = q3;
            }
            #pragma unroll
            for (int mi = 0; mi < MI; mi++)
                #pragma unroll
                for (int ni = 0; ni < NI; ni++)
                    mma16816(acc[mi][ni], af[mi], bf[ni]);
        }
    };

    #pragma unroll
    for (int s = 0; s < STAGES - 1; s++) { load_stage(s, s); CP_COMMIT(); }

    for (int t = 0; t < total; t++) {
        CP_WAIT(STAGES - 2);
        __syncthreads();
        if (t + STAGES - 1 < total) {
            load_stage(t + STAGES - 1, (t + STAGES - 1) % STAGES);
            CP_COMMIT();
        }
        compute_stage(t % STAGES);
    }

    if (MODE == 3) {
        float S[MI][2][3];
        #pragma unroll
        for (int mi = 0; mi < MI; mi++)
            #pragma unroll
            for (int h = 0; h < 2; h++)
                #pragma unroll
                for (int s = 0; s < 3; s++) S[mi][h][s] = 0.f;
        #pragma unroll
        for (int mi = 0; mi < MI; mi++) {
            int r0 = bm + wm * 32 + mi * 16 + (lane >> 2);
            #pragma unroll
            for (int ni = 0; ni < NI; ni++) {
                int c0 = bn + wn * 64 + ni * 8 + 2 * (lane & 3);
                #pragma unroll
                for (int q = 0; q < 4; q++) {
                    int gr = r0 + (q >> 1) * 8;
                    int gc = c0 + (q & 1);
                    float e = __expf(fmaf(acc[mi][ni][q], scale, -10.f));
                    if (gr == gc) Dg[gr] = e;
                    float e2 = e * e;
                    S[mi][q >> 1][0] += e;
                    S[mi][q >> 1][1] += e2;
                    S[mi][q >> 1][2] = fmaf(e2, e, S[mi][q >> 1][2]);
                }
            }
        }
        #pragma unroll
        for (int mi = 0; mi < MI; mi++)
            #pragma unroll
            for (int h = 0; h < 2; h++)
                #pragma unroll
                for (int s = 0; s < 3; s++) {
                    float v = S[mi][h][s];
                    v += __shfl_xor_sync(0xffffffffu, v, 1);
                    v += __shfl_xor_sync(0xffffffffu, v, 2);
                    S[mi][h][s] = v;
                }
        __syncthreads();
        float* sums = (float*)smraw;
        if ((lane & 3) == 0) {
            #pragma unroll
            for (int mi = 0; mi < MI; mi++)
                #pragma unroll
                for (int h = 0; h < 2; h++) {
                    int rib = wm * 32 + mi * 16 + (lane >> 2) + h * 8;
                    #pragma unroll
                    for (int s = 0; s < 3; s++)
                        sums[(wn * 128 + rib) * 3 + s] = S[mi][h][s];
                }
        }
        __syncthreads();
        if (tid < 128) {
            #pragma unroll
            for (int s = 0; s < 3; s++)
                P[((size_t)(bm + tid) * nbx + blockIdx.x) * 3 + s] =
                    sums[tid * 3 + s] + sums[(128 + tid) * 3 + s];
        }
        return;
    }

    if (MODE == 4) {
        // store raw dots
        #pragma unroll
        for (int mi = 0; mi < MI; mi++) {
            int r0 = bm + wm * 32 + mi * 16 + (lane >> 2);
            #pragma unroll
            for (int ni = 0; ni < NI; ni++) {
                int c0 = bn + wn * 64 + ni * 8 + 2 * (lane & 3);
                float2 u0 = { acc[mi][ni][0], acc[mi][ni][1] };
                float2 u1 = { acc[mi][ni][2], acc[mi][ni][3] };
                *(float2*)(Cf + (long)r0 * Ncols + c0) = u0;
                *(float2*)(Cf + (long)(r0 + 8) * Ncols + c0) = u1;
            }
        }
        // fused argmax
        #pragma unroll
        for (int mi = 0; mi < MI; mi++) {
            int r0 = bm + wm * 32 + mi * 16 + (lane >> 2);
            #pragma unroll
            for (int h = 0; h < 2; h++) {
                unsigned long long key = 0;
                #pragma unroll
                for (int ni = 0; ni < NI; ni++) {
                    int c0 = bn + wn * 64 + ni * 8 + 2 * (lane & 3);
                    unsigned long long k0 = packkey(acc[mi][ni][h * 2 + 0], c0);
                    unsigned long long k1 = packkey(acc[mi][ni][h * 2 + 1], c0 + 1);
                    if (k0 > key) key = k0;
                    if (k1 > key) key = k1;
                }
                #pragma unroll
                for (int o = 1; o <= 2; o <<= 1) {
                    unsigned long long ok = __shfl_xor_sync(0xffffffffu, key, o);
                    if (ok > key) key = ok;
                }
                if ((lane & 3) == 0) atomicMax(amax + r0 + h * 8, key);
            }
        }
        return;
    }

    #pragma unroll
    for (int mi = 0; mi < MI; mi++) {
        int r0 = bm + wm * 32 + mi * 16 + (lane >> 2);
        #pragma unroll
        for (int ni = 0; ni < NI; ni++) {
            int c0 = bn + wn * 64 + ni * 8 + 2 * (lane & 3);
            float d0 = acc[mi][ni][0], d1 = acc[mi][ni][1];
            float d2 = acc[mi][ni][2], d3 = acc[mi][ni][3];
            if (MODE == 0) {
                float* o = Cf + (size_t)zid * zstride;
                float2 u0 = { d0 * scale, d1 * scale };
                float2 u1 = { d2 * scale, d3 * scale };
                *(float2*)(o + (long)r0 * Ncols + c0) = u0;
                *(float2*)(o + (long)(r0 + 8) * Ncols + c0) = u1;
            } else if (MODE == 2) {
                float b0 = __ldg(bias + c0), b1 = __ldg(bias + c0 + 1);
                float v0 = fmaxf(d0 + b0, 0.f), v1 = fmaxf(d1 + b1, 0.f);
                float v2 = fmaxf(d2 + b0, 0.f), v3 = fmaxf(d3 + b1, 0.f);
                __nv_bfloat16 h0 = __float2bfloat16(v0), h1 = __float2bfloat16(v1);
                __nv_bfloat16 h2 = __float2bfloat16(v2), h3 = __float2bfloat16(v3);
                __nv_bfloat16 l0 = __float2bfloat16(v0 - __bfloat162float(h0));
                __nv_bfloat16 l1 = __float2bfloat16(v1 - __bfloat162float(h1));
                __nv_bfloat16 l2 = __float2bfloat16(v2 - __bfloat162float(h2));
                __nv_bfloat16 l3 = __float2bfloat16(v3 - __bfloat162float(h3));
                __nv_bfloat162 hp0; hp0.x = h0; hp0.y = h1;
                __nv_bfloat162 hp1; hp1.x = h2; hp1.y = h3;
                __nv_bfloat162 lp0; lp0.x = l0; lp0.y = l1;
                __nv_bfloat162 lp1; lp1.x = l2; lp1.y = l3;
                *(__nv_bfloat162*)(C2 + (long)r0 * ldC2 + c0) = hp0;
                *(__nv_bfloat162*)(C2 + (long)(r0 + 8) * ldC2 + c0) = hp1;
                *(__nv_bfloat162*)(C2 + (long)r0 * ldC2 + loOff + c0) = lp0;
                *(__nv_bfloat162*)(C2 + (long)(r0 + 8) * ldC2 + loOff + c0) = lp1;
            }
        }
    }
}

// ---------------- fp32 -> bf16 hi/lo split -----------------------------------
__global__ void cvt_split(const float4* __restrict__ in, __nv_bfloat16* __restrict__ out,
                          int kshift, int n4)
{
    int i = blockIdx.x * blockDim.x + threadIdx.x;
    if (i >= n4) return;
    float4 v = in[i];
    long e = (long)i * 4;
    int K = 1 << kshift;
    long r = e >> kshift;
    int k = (int)(e & (K - 1));
    long base = r * (2L * K) + k;
    float f[4] = {v.x, v.y, v.z, v.w};
    __nv_bfloat16 h[4], l[4];
    #pragma unroll
    for (int j = 0; j < 4; j++) {
        h[j] = __float2bfloat16(f[j]);
        l[j] = __float2bfloat16(f[j] - __bfloat162float(h[j]));
    }
    __nv_bfloat162 p0; p0.x = h[0]; p0.y = h[1];
    __nv_bfloat162 p1; p1.x = h[2]; p1.y = h[3];
    __nv_bfloat162 q0; q0.x = l[0]; q0.y = l[1];
    __nv_bfloat162 q1; q1.x = l[2]; q1.y = l[3];
    *(__nv_bfloat162*)(out + base + 0) = p0;
    *(__nv_bfloat162*)(out + base + 2) = p1;
    *(__nv_bfloat162*)(out + base + K + 0) = q0;
    *(__nv_bfloat162*)(out + base + K + 2) = q1;
}

// ---------------- l2 normalize + split ---------------------------------------
__global__ void l2norm_split(const float* __restrict__ in,
                             __nv_bfloat16* __restrict__ out2,
                             float* __restrict__ outf)
{
    int row = blockIdx.x;
    const float4* p = (const float4*)(in + (long)row * EE);
    float4 v = p[threadIdx.x];
    float ss = v.x*v.x + v.y*v.y + v.z*v.z + v.w*v.w;
    float tot = blkRedSum(ss);
    float s = 1.f / fmaxf(sqrtf(tot), 1e-12f);
    v.x *= s; v.y *= s; v.z *= s; v.w *= s;
    if (outf) ((float4*)(outf + (long)row * EE))[threadIdx.x] = v;
    long base = (long)row * (2 * EE) + threadIdx.x * 4;
    float f[4] = {v.x, v.y, v.z, v.w};
    __nv_bfloat16 h[4], l[4];
    #pragma unroll
    for (int j = 0; j < 4; j++) {
        h[j] = __float2bfloat16(f[j]);
        l[j] = __float2bfloat16(f[j] - __bfloat162float(h[j]));
    }
    __nv_bfloat162 p0; p0.x = h[0]; p0.y = h[1];
    __nv_bfloat162 p1; p1.x = h[2]; p1.y = h[3];
    __nv_bfloat162 q0; q0.x = l[0]; q0.y = l[1];
    __nv_bfloat162 q1; q1.x = l[2]; q1.y = l[3];
    *(__nv_bfloat162*)(out2 + base + 0) = p0;
    *(__nv_bfloat162*)(out2 + base + 2) = p1;
    *(__nv_bfloat162*)(out2 + base + EE + 0) = q0;
    *(__nv_bfloat162*)(out2 + base + EE + 2) = q1;
}

// ---------------- merge split-K halves + bias, normalize, split --------------
__global__ void l2norm_merge(const float* __restrict__ za, const float* __restrict__ zb,
                             const float* __restrict__ bias,
                             __nv_bfloat16* __restrict__ out2)
{
    int row = blockIdx.x;
    float4 a = ((const float4*)(za + (long)row * EE))[threadIdx.x];
    float4 b = ((const float4*)(zb + (long)row * EE))[threadIdx.x];
    float4 c = ((const float4*)bias)[threadIdx.x];
    float4 v = { a.x + b.x + c.x, a.y + b.y + c.y, a.z + b.z + c.z, a.w + b.w + c.w };
    float ss = v.x*v.x + v.y*v.y + v.z*v.z + v.w*v.w;
    float tot = blkRedSum(ss);
    float s = 1.f / fmaxf(sqrtf(tot), 1e-12f);
    v.x *= s; v.y *= s; v.z *= s; v.w *= s;
    long base = (long)row * (2 * EE) + threadIdx.x * 4;
    float f[4] = {v.x, v.y, v.z, v.w};
    __nv_bfloat16 h[4], l[4];
    #pragma unroll
    for (int j = 0; j < 4; j++) {
        h[j] = __float2bfloat16(f[j]);
        l[j] = __float2bfloat16(f[j] - __bfloat162float(h[j]));
    }
    __nv_bfloat162 p0; p0.x = h[0]; p0.y = h[1];
    __nv_bfloat162 p1; p1.x = h[2]; p1.y = h[3];
    __nv_bfloat162 q0; q0.x = l[0]; q0.y = l[1];
    __nv_bfloat162 q1; q1.x = l[2]; q1.y = l[3];
    *(__nv_bfloat162*)(out2 + base + 0) = p0;
    *(__nv_bfloat162*)(out2 + base + 2) = p1;
    *(__nv_bfloat162*)(out2 + base + EE + 0) = q0;
    *(__nv_bfloat162*)(out2 + base + EE + 2) = q1;
}

// ---------------- init -------------------------------------------------------
__global__ void init_bufs(unsigned long long* a, int n, int* cnt, int m)
{
    int i = blockIdx.x * blockDim.x + threadIdx.x;
    if (i < n) a[i] = 0ull;
    if (i < m) cnt[i] = 0;
}

// ---------------- histogram of argmax indices --------------------------------
__global__ void hist_ind(const unsigned long long* __restrict__ amax, int* __restrict__ cnt)
{
    int i = blockIdx.x * blockDim.x + threadIdx.x;
    if (i < BB) {
        int idx = (int)(~(uint32_t)(amax[i] & 0xffffffffull));
        atomicAdd(cnt + idx, 1);
    }
}

// ---------------- gather output ----------------------------------------------
__global__ void gather_out(float* __restrict__ out, const float* __restrict__ ns,
                           const unsigned long long* __restrict__ amax)
{
    int row = blockIdx.x;
    int idx = (int)(~(uint32_t)(amax[row] & 0xffffffffull));
    ((float4*)(out + (long)row * EE))[threadIdx.x] =
        ((const float4*)(ns + (long)idx * EE))[threadIdx.x];
}

// ---------------- compat CE via histogram-weighted scores pass ---------------
// compat[i,j] = 10*scores[i, ind[j]]; row CE needs S1..S3 = sum_j e^m = sum_k cnt[k]*e_k^m
__global__ __launch_bounds__(256)
void compat_ce(const float* __restrict__ S, const int* __restrict__ cnt,
               const unsigned long long* __restrict__ amax, float* __restrict__ rl)
{
    int row = blockIdx.x;
    const float* p = S + (size_t)row * NSN;
    float S1 = 0.f, S2 = 0.f, S3 = 0.f;
    #pragma unroll
    for (int it = 0; it < NSN / 256; it++) {
        int k = threadIdx.x + it * 256;
        float c = (float)cnt[k];
        float s = fmaf(p[k], INV_T, -10.f);
        float e = (it & 1) ? fexp(s) : __expf(s);
        float ce = c * e;
        S1 += ce;
        S2 += ce * e;
        S3 += ce * e * e;
    }
    S1 = blkRedSum(S1);
    S2 = blkRedSum(S2);
    S3 = blkRedSum(S3);
    if (threadIdx.x == 0) {
        int idx = (int)(~(uint32_t)(amax[row] & 0xffffffffull));
        float ed = __expf(fmaf(p[idx], INV_T, -10.f));
        float Z = S1;
        float t = (float)BB + 1.0f + S2 / (2.0f * Z * Z) + S3 / (6.0f * Z * Z * Z);
        rl[row] = -(ed / Z - logf(t));
    }
}

// ---------------- CE finish (abssim) -----------------------------------------
__global__ void ce_finish(const float* __restrict__ P, int nbx,
                          const float* __restrict__ Dg, int cols,
                          float* __restrict__ rl, int rows)
{
    int r = blockIdx.x * blockDim.x + threadIdx.x;
    if (r >= rows) return;
    float S1 = 0.f, S2 = 0.f, S3 = 0.f;
    const float* p = P + (size_t)r * nbx * 3;
    for (int b = 0; b < nbx; b++) {
        S1 += p[b * 3 + 0];
        S2 += p[b * 3 + 1];
        S3 += p[b * 3 + 2];
    }
    float Z = S1;
    float t = (float)cols + 1.0f + S2 / (2.0f * Z * Z) + S3 / (6.0f * Z * Z * Z);
    float pd = Dg[r] / Z;
    rl[r] = -(pd - logf(t));
}

// ---------------- final loss -------------------------------------------------
__global__ void final_loss(float* __restrict__ out, long idx)
{
    float s1 = 0.f;
    for (int i = threadIdx.x; i < BB; i += 1024) s1 += g_rl1[i];
    float s2 = (threadIdx.x < NSN) ? g_rl2[threadIdx.x] : 0.f;
    float v = s1 * (1.0f / (float)BB) + s2 * (1.0f / (float)NSN);
    v = blkRedSum(v);
    if (threadIdx.x == 0) out[idx] = v;
}

// ---------------- launch ------------------------------------------------------
extern "C" void kernel_launch(void* const* d_in, const int* in_sizes, int n_in,
                              void* d_out, int out_size)
{
    const float* x          = (const float*)d_in[0];
    const float* body_W     = (const float*)d_in[1];
    const float* body_b     = (const float*)d_in[2];
    const float* fc_W       = (const float*)d_in[3];
    const float* fc_b       = (const float*)d_in[4];
    const float* abs_states = (const float*)d_in[5];
    float* out = (float*)d_out;

    __nv_bfloat16 *x2, *w1, *w2, *f2, *nz2, *ns2;
    float *zsp, *ns, *scores, *p2, *d2, *rl1, *rl2;
    unsigned long long* amax;
    int* cnt;
    cudaGetSymbolAddress((void**)&x2,  g_x2);
    cudaGetSymbolAddress((void**)&w1,  g_w1);
    cudaGetSymbolAddress((void**)&w2,  g_w2);
    cudaGetSymbolAddress((void**)&f2,  g_f2);
    cudaGetSymbolAddress((void**)&zsp, g_zsp);
    cudaGetSymbolAddress((void**)&nz2, g_nz2);
    cudaGetSymbolAddress((void**)&ns,  g_ns);
    cudaGetSymbolAddress((void**)&ns2, g_ns2);
    cudaGetSymbolAddress((void**)&scores, g_scores);
    cudaGetSymbolAddress((void**)&amax, g_amax);
    cudaGetSymbolAddress((void**)&cnt, g_cnt);
    cudaGetSymbolAddress((void**)&p2,  g_p2);
    cudaGetSymbolAddress((void**)&d2,  g_d2);
    cudaGetSymbolAddress((void**)&rl1, g_rl1);
    cudaGetSymbolAddress((void**)&rl2, g_rl2);

    static cudaStream_t s2 = nullptr;
    static cudaEvent_t eNS = nullptr, eW2 = nullptr, e1 = nullptr;
    if (!s2) {
        cudaStreamCreateWithFlags(&s2, cudaStreamNonBlocking);
        cudaEventCreateWithFlags(&eNS, cudaEventDisableTiming);
        cudaEventCreateWithFlags(&eW2, cudaEventDisableTiming);
        cudaEventCreateWithFlags(&e1, cudaEventDisableTiming);
    }

    const int SMEMB = 65536;
    cudaFuncSetAttribute(gemm_k<2,3,1>, cudaFuncAttributeMaxDynamicSharedMemorySize, SMEMB);
    cudaFuncSetAttribute(gemm_k<0,3,2>, cudaFuncAttributeMaxDynamicSharedMemorySize, SMEMB);
    cudaFuncSetAttribute(gemm_k<4,3,1>, cudaFuncAttributeMaxDynamicSharedMemorySize, SMEMB);
    cudaFuncSetAttribute(gemm_k<3,1,1>, cudaFuncAttributeMaxDynamicSharedMemorySize, SMEMB);

    // main: init + conversions + abs_states normalize
    init_bufs<<<(BB + 255) / 256, 256>>>(amax, BB, cnt, NSN);
    cvt_split<<<(BB * INF_ / 4 + 255) / 256, 256>>>((const float4*)x, x2, 11, BB * INF_ / 4);
    cvt_split<<<(FEATF * INF_ / 4 + 255) / 256, 256>>>((const float4*)body_W, w1, 11, FEATF * INF_ / 4);
    l2norm_split<<<NSN, 128>>>(abs_states, ns2, ns);
    cudaEventRecord(eNS, 0);

    // s2: fc_W conversion + abssim CE branch (overlaps GEMM1)
    cudaStreamWaitEvent(s2, eNS, 0);
    cvt_split<<<(EE * FEATF / 4 + 255) / 256, 256, 0, s2>>>((const float4*)fc_W, w2, 11, EE * FEATF / 4);
    cudaEventRecord(eW2, s2);
    gemm_k<3,1,1><<<dim3(NSN / 128, NSN / 128), 256, SMEMB, s2>>>(
        ns2, 2 * EE, ns2, 2 * EE, EE, NSN, nullptr, INV_T,
        nullptr, 0, nullptr, 0, 0, p2, 8, d2, nullptr);
    ce_finish<<<(NSN + 255) / 256, 256, 0, s2>>>(p2, 8, d2, NSN, rl2, NSN);
    cudaEventRecord(e1, s2);

    // 1) feat = relu(x @ body_W^T + b) -> split bf16
    gemm_k<2,3,1><<<dim3(FEATF / 128, BB / 128), 256, SMEMB>>>(
        x2, 2 * INF_, w1, 2 * INF_, INF_, FEATF, body_b, 1.f,
        nullptr, 0, f2, 2 * FEATF, FEATF, nullptr, 0, nullptr, nullptr);

    // 2) z = feat @ fc_W^T (split-K=2)
    cudaStreamWaitEvent(0, eW2, 0);
    gemm_k<0,3,2><<<dim3(EE / 128, BB / 128, 2), 256, SMEMB>>>(
        f2, 2 * FEATF, w2, 2 * FEATF, FEATF, EE, nullptr, 1.f,
        zsp, (size_t)BB * EE, nullptr, 0, 0, nullptr, 0, nullptr, nullptr);

    // 3) merge halves + fc_b, normalize, split
    l2norm_merge<<<BB, 128>>>(zsp, zsp + (size_t)BB * EE, fc_b, nz2);

    // 4) scores (stored raw) + fused argmax
    gemm_k<4,3,1><<<dim3(NSN / 128, BB / 128), 256, SMEMB>>>(
        nz2, 2 * EE, ns2, 2 * EE, EE, NSN, nullptr, 1.f,
        scores, 0, nullptr, 0, 0, nullptr, 0, nullptr, amax);

    // 5) histogram + output gather
    hist_ind<<<(BB + 255) / 256, 256>>>(amax, cnt);
    gather_out<<<BB, 128>>>(out, ns, amax);

    // 6) compat CE directly from scores + histogram (no GEMM!)
    compat_ce<<<BB, 256>>>(scores, cnt, amax, rl1);

    // join + final loss
    cudaStreamWaitEvent(0, e1, 0);
    if (out_size > BB * EE) {
        final_loss<<<1, 1024>>>(out, (long)BB * EE);
    }
}